// round 11
// baseline (speedup 1.0000x reference)
#include <cuda_runtime.h>
#include <cuda_bf16.h>
#include <math.h>
#include <stdint.h>

#define B_    8
#define NH    8
#define T_    8
#define HD    32
#define C_    256
#define N_    8192
#define HW    1024
#define BHT   512            // B*NH*T
#define M_TOT 65536          // B*N

// ---------------- scratch (static device globals; no allocation) ----------------
__device__ __nv_bfloat16 g_qh[(size_t)BHT * HW * 32];  // q hi [img][px][ch]
__device__ __nv_bfloat16 g_ql[(size_t)BHT * HW * 32];
__device__ __nv_bfloat16 g_kh[(size_t)BHT * HW * 32];  // k hi (shifted) [img][px][ch]
__device__ __nv_bfloat16 g_kl[(size_t)BHT * HW * 32];
__device__ __nv_bfloat16 g_vhi[(size_t)M_TOT * C_];
__device__ __nv_bfloat16 g_vlo[(size_t)M_TOT * C_];
__device__ __nv_bfloat16 g_wqk_hi[512 * 256];
__device__ __nv_bfloat16 g_wqk_lo[512 * 256];
__device__ __nv_bfloat16 g_wpj_hi[256 * 256];
__device__ __nv_bfloat16 g_wpj_lo[256 * 256];
__device__ __nv_bfloat16 g_wcT_hi[32 * 64];            // w_corr [e][j'=dy*8+dx] padded
__device__ __nv_bfloat16 g_wcT_lo[32 * 64];

// ======================= asm helpers ==================
__device__ __forceinline__ uint32_t smem_u32(const void* p) {
    uint32_t a;
    asm("{ .reg .u64 t; cvta.to.shared.u64 t, %1; cvt.u32.u64 %0, t; }" : "=r"(a) : "l"(p));
    return a;
}
__device__ __forceinline__ void cp16(uint32_t saddr, const void* g) {
    asm volatile("cp.async.cg.shared.global [%0], [%1], 16;" :: "r"(saddr), "l"(g));
}
#define CP_COMMIT() asm volatile("cp.async.commit_group;" ::: "memory")
#define CP_WAIT1()  asm volatile("cp.async.wait_group 1;" ::: "memory")
#define CP_WAIT0()  asm volatile("cp.async.wait_group 0;" ::: "memory")

#define LDSM4(r0, r1, r2, r3, addr) \
    asm volatile("ldmatrix.sync.aligned.m8n8.x4.shared.b16 {%0,%1,%2,%3}, [%4];" \
                 : "=r"(r0), "=r"(r1), "=r"(r2), "=r"(r3) : "r"(addr))
#define MMA16816(c, a0, a1, a2, a3, b0, b1) \
    asm volatile("mma.sync.aligned.m16n8k16.row.col.f32.bf16.bf16.f32 " \
                 "{%0,%1,%2,%3},{%4,%5,%6,%7},{%8,%9},{%0,%1,%2,%3};" \
                 : "+f"((c)[0]), "+f"((c)[1]), "+f"((c)[2]), "+f"((c)[3]) \
                 : "r"(a0), "r"(a1), "r"(a2), "r"(a3), "r"(b0), "r"(b1))

__device__ __forceinline__ void split_bf16x2(float a, float b, uint32_t& hi, uint32_t& lo) {
    __nv_bfloat162 hb = __floats2bfloat162_rn(a, b);
    float r0 = a - __bfloat162float(__low2bfloat16(hb));
    float r1 = b - __bfloat162float(__high2bfloat16(hb));
    __nv_bfloat162 lb = __floats2bfloat162_rn(r0, r1);
    hi = *(uint32_t*)&hb;
    lo = *(uint32_t*)&lb;
}

// =================================================================================
__global__ void __launch_bounds__(256)
conv_split(const float4* __restrict__ in, uint2* __restrict__ hi,
           uint2* __restrict__ lo, int n4)
{
    int i = blockIdx.x * 256 + threadIdx.x;
    if (i >= n4) return;
    float4 f = in[i];
    uint32_t h0, l0, h1, l1;
    split_bf16x2(f.x, f.y, h0, l0);
    split_bf16x2(f.z, f.w, h1, l1);
    hi[i] = make_uint2(h0, h1);
    lo[i] = make_uint2(l0, l1);
}

// w_corr [32 e][49 j] -> padded [32 e][64 j'] with j' = dy*8+dx
__global__ void __launch_bounds__(256)
prep_w(const float* __restrict__ wc, __nv_bfloat16* __restrict__ wh,
       __nv_bfloat16* __restrict__ wl)
{
    int i = blockIdx.x * 256 + threadIdx.x;
    if (i >= 32 * 64) return;
    int e = i >> 6, jp = i & 63;
    int dy = jp >> 3, dx = jp & 7;
    float v = (dy < 7 && dx < 7) ? wc[e * 49 + dy * 7 + dx] : 0.f;
    __nv_bfloat16 h = __float2bfloat16(v);
    float r = v - __bfloat162float(h);
    wh[i] = h;
    wl[i] = __float2bfloat16(r);
}

// =================================================================================
// GEMM constants (shared by gemm_qk and gemm_proj). Block 128x128, BK=32, K=256.
// =================================================================================
#define KGEMM 256
#define NTILES 8
#define GM_STAGE 32768
#define GM_SMEM  (3 * GM_STAGE)    // 96 KB (both gemm kernels)

// ---- gemm_proj path: pre-split A/B, 3-stage 4-buffer stages (proven) ----
__device__ __forceinline__ void stage_load(
    uint32_t sbase, const __nv_bfloat16* __restrict__ Ahi,
    const __nv_bfloat16* __restrict__ Alo, const __nv_bfloat16* __restrict__ Bhi,
    const __nv_bfloat16* __restrict__ Blo, int m0, int n0, int kt, int tid)
{
    int t = tid * 2;
    int row = t >> 2;
    int cb  = t & 3;
#pragma unroll
    for (int j = 0; j < 2; j++) {
        int c16 = cb + j;
        uint32_t soff = (uint32_t)(row * 64 + ((c16 ^ ((row >> 1) & 3)) << 4));
        size_t ga = (size_t)row * KGEMM + kt * 32 + c16 * 8;
        cp16(sbase +     0 + soff, Ahi + (size_t)m0 * KGEMM + ga);
        cp16(sbase +  8192 + soff, Alo + (size_t)m0 * KGEMM + ga);
        cp16(sbase + 16384 + soff, Bhi + (size_t)n0 * KGEMM + ga);
        cp16(sbase + 24576 + soff, Blo + (size_t)n0 * KGEMM + ga);
    }
}

// ks-body shared by both kernels: A at aBase (hi) / aBase+8192 (lo), B at bBase.
__device__ __forceinline__ void mma_ks_body(
    uint32_t aBase, uint32_t bBase, int ks, int lane, int wm, int wn,
    uint32_t bsel, float acc[4][4][4])
{
    const uint32_t l2 = lane & 15;
    uint32_t aaddr[4], baddr[4];
    {
        uint32_t achk = (uint32_t)(ks * 2) + (lane >> 4);
#pragma unroll
        for (int i = 0; i < 4; i++) {
            uint32_t r = wm + l2 + i * 16;
            aaddr[i] = aBase + r * 64 + ((achk ^ ((r >> 1) & 3)) << 4);
        }
        uint32_t bchk = (uint32_t)(ks * 2) + ((l2 >> 3) & 1);
#pragma unroll
        for (int j = 0; j < 4; j++) {
            uint32_t r = wn + (l2 & 7) + j * 8;
            baddr[j] = bBase + r * 64 + ((bchk ^ ((r >> 1) & 3)) << 4) + bsel;
        }
    }
    uint32_t a[4][4], al[4][4], b4[4][4];
#pragma unroll
    for (int i = 0; i < 4; i++) LDSM4(a[i][0], a[i][1], a[i][2], a[i][3], aaddr[i]);
#pragma unroll
    for (int j = 0; j < 4; j++) LDSM4(b4[j][0], b4[j][1], b4[j][2], b4[j][3], baddr[j]);
#pragma unroll
    for (int i = 0; i < 4; i++) LDSM4(al[i][0], al[i][1], al[i][2], al[i][3], aaddr[i] + 8192);
#pragma unroll
    for (int i = 0; i < 4; i++)
#pragma unroll
        for (int j = 0; j < 4; j++)
            MMA16816(acc[i][j], a[i][0], a[i][1], a[i][2], a[i][3], b4[j][0], b4[j][1]);
#pragma unroll
    for (int i = 0; i < 4; i++)
#pragma unroll
        for (int j = 0; j < 4; j++)
            MMA16816(acc[i][j], a[i][0], a[i][1], a[i][2], a[i][3], b4[j][2], b4[j][3]);
#pragma unroll
    for (int i = 0; i < 4; i++)
#pragma unroll
        for (int j = 0; j < 4; j++)
            MMA16816(acc[i][j], al[i][0], al[i][1], al[i][2], al[i][3], b4[j][0], b4[j][1]);
}

__device__ __forceinline__ void gemm_mainloop(
    const __nv_bfloat16* __restrict__ Ahi, const __nv_bfloat16* __restrict__ Alo,
    const __nv_bfloat16* __restrict__ Bhi, const __nv_bfloat16* __restrict__ Blo,
    uint32_t sb, int m0, int n0, int tid, int lane, int wm, int wn,
    float acc[4][4][4])
{
#pragma unroll
    for (int i = 0; i < 4; i++)
#pragma unroll
        for (int j = 0; j < 4; j++)
#pragma unroll
            for (int q = 0; q < 4; q++) acc[i][j][q] = 0.f;

    stage_load(sb,            Ahi, Alo, Bhi, Blo, m0, n0, 0, tid);
    CP_COMMIT();
    stage_load(sb + GM_STAGE, Ahi, Alo, Bhi, Blo, m0, n0, 1, tid);
    CP_COMMIT();

    const uint32_t bsel = (lane & 16) ? 8192u : 0u;

    int stage = 0;
    int lstage = 2;
    for (int kt = 0; kt < NTILES; kt++) {
        CP_WAIT1();
        __syncthreads();
        if (kt + 2 < NTILES)
            stage_load(sb + lstage * GM_STAGE, Ahi, Alo, Bhi, Blo, m0, n0, kt + 2, tid);
        CP_COMMIT();
        lstage = stage;

        const uint32_t sa = sb + stage * GM_STAGE;
        stage = (stage == 2) ? 0 : stage + 1;

#pragma unroll
        for (int ks = 0; ks < 2; ks++)
            mma_ks_body(sa, sa + 16384, ks, lane, wm, wn, bsel, acc);
    }
}

// =================================================================================
// GEMM1 fused: A = fp32 x (converted to bf16 hi/lo IN-KERNEL), B = w_qk hi/lo.
// smem: A32 2-stage @0/16384 (16KB each); Ahi @32768, Alo @40960 (single-buffer);
// B 3-stage @49152 + s*16384 (Bhi +0, Blo +8192). Total 96 KB.
// Epilogue: L2-normalize + temporal shift; emits q/k as bf16 hi/lo [img][px][ch].
// =================================================================================
#define QK_AHI 32768u
#define QK_B0  49152u

__device__ __forceinline__ void qk_load_A32(
    char* smg, uint32_t sbase, const float* __restrict__ X, int m0, int kt, int tid)
{
#pragma unroll
    for (int j = 0; j < 4; j++) {
        int c = tid * 4 + j;                 // 0..1023
        int row = c >> 3, kc = c & 7;
        cp16(sbase + c * 16, X + (size_t)(m0 + row) * KGEMM + kt * 32 + kc * 4);
    }
}
__device__ __forceinline__ void qk_load_B(
    uint32_t sbase, const __nv_bfloat16* __restrict__ Bhi,
    const __nv_bfloat16* __restrict__ Blo, int n0, int kt, int tid)
{
    int row = tid >> 1;
    int cb  = (tid * 2) & 3;
#pragma unroll
    for (int j = 0; j < 2; j++) {
        int c16 = cb + j;
        uint32_t soff = (uint32_t)(row * 64 + ((c16 ^ ((row >> 1) & 3)) << 4));
        size_t ga = (size_t)(n0 + row) * KGEMM + kt * 32 + c16 * 8;
        cp16(sbase +    0 + soff, Bhi + ga);
        cp16(sbase + 8192 + soff, Blo + ga);
    }
}

__global__ void __launch_bounds__(256, 2)
gemm_qk(const float* __restrict__ X,
        const __nv_bfloat16* __restrict__ Bhi, const __nv_bfloat16* __restrict__ Blo,
        __nv_bfloat16* __restrict__ qh, __nv_bfloat16* __restrict__ ql,
        __nv_bfloat16* __restrict__ kh, __nv_bfloat16* __restrict__ kl)
{
    const bool is_k = (blockIdx.x >= 2);
    const int tt_blk = (blockIdx.y >> 3) & 7;
    if (is_k && tt_blk == 0) return;        // dead k tile (shifted away)

    extern __shared__ char smg[];
    const uint32_t sb = smem_u32(smg);
    const int tid = threadIdx.x;
    const int lane = tid & 31;
    const int wid = tid >> 5;
    const int m0 = blockIdx.y * 128;
    const int n0 = blockIdx.x * 128;
    const int wm = (wid >> 2) * 64;
    const int wn = (wid & 3) * 32;

    float acc[4][4][4];
#pragma unroll
    for (int i = 0; i < 4; i++)
#pragma unroll
        for (int j = 0; j < 4; j++)
#pragma unroll
            for (int q = 0; q < 4; q++) acc[i][j][q] = 0.f;

    qk_load_A32(smg, sb + 0,     X, m0, 0, tid);
    qk_load_B(sb + QK_B0,            Bhi, Blo, n0, 0, tid);
    CP_COMMIT();
    qk_load_A32(smg, sb + 16384, X, m0, 1, tid);
    qk_load_B(sb + QK_B0 + 16384,    Bhi, Blo, n0, 1, tid);
    CP_COMMIT();

    const uint32_t bsel = (lane & 16) ? 8192u : 0u;
    const int crow = tid >> 1;
    const int chalf = tid & 1;

    int bstage = 0;
    int blstage = 2;
    for (int kt = 0; kt < NTILES; kt++) {
        CP_WAIT1();
        __syncthreads();

        // convert A32(kt&1) -> Ahi/Alo (single buffer; safe: all warps past mma(kt-1))
        {
            const float4* st = (const float4*)(smg + (kt & 1) * 16384 + crow * 128 + chalf * 64);
            float4 f0 = st[0], f1 = st[1], f2 = st[2], f3 = st[3];
            float f[16] = {f0.x, f0.y, f0.z, f0.w, f1.x, f1.y, f1.z, f1.w,
                           f2.x, f2.y, f2.z, f2.w, f3.x, f3.y, f3.z, f3.w};
            uint32_t hw[8], lw[8];
#pragma unroll
            for (int p = 0; p < 8; p++) split_bf16x2(f[2 * p], f[2 * p + 1], hw[p], lw[p]);
#pragma unroll
            for (int jj = 0; jj < 2; jj++) {
                int c16 = chalf * 2 + jj;
                uint32_t soff = (uint32_t)(crow * 64 + ((c16 ^ ((crow >> 1) & 3)) << 4));
                *(uint4*)(smg + QK_AHI + soff)        = make_uint4(hw[4*jj], hw[4*jj+1], hw[4*jj+2], hw[4*jj+3]);
                *(uint4*)(smg + QK_AHI + 8192 + soff) = make_uint4(lw[4*jj], lw[4*jj+1], lw[4*jj+2], lw[4*jj+3]);
            }
        }
        __syncthreads();

        // issue next loads (A32 into stage kt&1 — just freed; B into blstage)
        if (kt + 2 < NTILES) {
            qk_load_A32(smg, sb + (kt & 1) * 16384, X, m0, kt + 2, tid);
            qk_load_B(sb + QK_B0 + blstage * 16384, Bhi, Blo, n0, kt + 2, tid);
        }
        CP_COMMIT();
        blstage = bstage;

        const uint32_t saB = sb + QK_B0 + bstage * 16384;
        bstage = (bstage == 2) ? 0 : bstage + 1;

#pragma unroll
        for (int ks = 0; ks < 2; ks++)
            mma_ks_body(sb + QK_AHI, saB, ks, lane, wm, wn, bsel, acc);
    }

    // ---------------- epilogue: normalize + shift + emit bf16 hi/lo ----------------
    const int head = (((n0 & 255) + wn) >> 5);

#pragma unroll
    for (int i = 0; i < 4; i++) {
#pragma unroll
        for (int h = 0; h < 2; h++) {
            float v0[4], v1[4];
            float ss = 0.f;
#pragma unroll
            for (int j = 0; j < 4; j++) {
                v0[j] = acc[i][j][2 * h];
                v1[j] = acc[i][j][2 * h + 1];
                ss += v0[j] * v0[j] + v1[j] * v1[j];
            }
            ss += __shfl_xor_sync(0xffffffffu, ss, 1);
            ss += __shfl_xor_sync(0xffffffffu, ss, 2);
            float inv = 1.0f / fmaxf(sqrtf(ss), 1e-12f);

            int r = m0 + wm + i * 16 + (lane >> 2) + h * 8;
            int b  = r >> 13;
            int tt = (r >> 10) & 7;
            int p  = r & 1023;

            uint32_t hw[4], lw[4];
#pragma unroll
            for (int j = 0; j < 4; j++)
                split_bf16x2(v0[j] * inv, v1[j] * inv, hw[j], lw[j]);

            if (!is_k) {
                size_t base = ((size_t)(b * 64 + head * 8 + tt) * HW + p) * 32;
#pragma unroll
                for (int j = 0; j < 4; j++) {
                    int col = j * 8 + (lane & 3) * 2;
                    *(uint32_t*)(qh + base + col) = hw[j];
                    *(uint32_t*)(ql + base + col) = lw[j];
                }
            } else {
                if (tt >= 1) {
                    size_t base = ((size_t)(b * 64 + head * 8 + (tt - 1)) * HW + p) * 32;
#pragma unroll
                    for (int j = 0; j < 4; j++) {
                        int col = j * 8 + (lane & 3) * 2;
                        *(uint32_t*)(kh + base + col) = hw[j];
                        *(uint32_t*)(kl + base + col) = lw[j];
                    }
                }
                if (tt == 7) {
                    size_t base = ((size_t)(b * 64 + head * 8 + 7) * HW + p) * 32;
#pragma unroll
                    for (int j = 0; j < 4; j++) {
                        int col = j * 8 + (lane & 3) * 2;
                        *(uint32_t*)(kh + base + col) = hw[j];
                        *(uint32_t*)(kl + base + col) = lw[j];
                    }
                }
            }
        }
    }
}

// =================================================================================
// GEMM4: out = v @ w_proj^T + bias, fp32 out (unchanged proven path)
// =================================================================================
__global__ void __launch_bounds__(256, 2)
gemm_proj(const __nv_bfloat16* __restrict__ Ahi, const __nv_bfloat16* __restrict__ Alo,
          const __nv_bfloat16* __restrict__ Bhi, const __nv_bfloat16* __restrict__ Blo,
          const float* __restrict__ bias, float* __restrict__ C, int ldc)
{
    extern __shared__ char smg[];
    const uint32_t sb = smem_u32(smg);
    const int tid = threadIdx.x;
    const int lane = tid & 31;
    const int wid = tid >> 5;
    const int m0 = blockIdx.y * 128;
    const int n0 = blockIdx.x * 128;
    const int wm = (wid >> 2) * 64;
    const int wn = (wid & 3) * 32;

    float acc[4][4][4];
    gemm_mainloop(Ahi, Alo, Bhi, Blo, sb, m0, n0, tid, lane, wm, wn, acc);

#pragma unroll
    for (int j = 0; j < 4; j++) {
        int c = n0 + wn + j * 8 + (lane & 3) * 2;
        float b0 = bias[c], b1 = bias[c + 1];
#pragma unroll
        for (int i = 0; i < 4; i++) {
            int r = m0 + wm + i * 16 + (lane >> 2);
            *(float2*)(C + (size_t)r * ldc + c) =
                make_float2(acc[i][j][0] + b0, acc[i][j][1] + b1);
            *(float2*)(C + (size_t)(r + 8) * ldc + c) =
                make_float2(acc[i][j][2] + b0, acc[i][j][3] + b1);
        }
    }
}

// =================================================================================
// corr_proj: banded tensor-core 7x7 correlation FUSED with (49->32) projection.
// (unchanged from R10 — proven at 381 µs)
// =================================================================================
#define CPK_KH 32768
#define CPK_KL 68608
#define CPK_WH 104448
#define CPK_WL 108544
#define CPK_CS 112640
#define CPK_SB 178176
#define CPK_SMEM 204800

__global__ void __launch_bounds__(512)
corr_proj(const __nv_bfloat16* __restrict__ qh, const __nv_bfloat16* __restrict__ ql,
          const __nv_bfloat16* __restrict__ kh, const __nv_bfloat16* __restrict__ kl,
          const __nv_bfloat16* __restrict__ wch, const __nv_bfloat16* __restrict__ wcl,
          const float* __restrict__ bc,
          __nv_bfloat16* __restrict__ vhi, __nv_bfloat16* __restrict__ vlo)
{
    extern __shared__ char sm[];
    const uint32_t sb = smem_u32(sm);
    const int tid  = threadIdx.x;
    const int lane = tid & 31;
    const int w    = tid >> 5;
    const int img  = blockIdx.x >> 2;
    const int yq   = (blockIdx.x & 3) * 8;

    for (int i = tid; i < 4480; i += 512)
        ((uint4*)(sm + CPK_KH))[i] = make_uint4(0, 0, 0, 0);
    __syncthreads();

    for (int i = tid; i < 2048; i += 512) {
        int hl = i >> 10;
        int px = (i >> 2) & 255;
        int c  = i & 3;
        const __nv_bfloat16* src = (hl ? ql : qh) +
            ((size_t)img * HW + yq * 32 + px) * 32 + c * 8;
        uint32_t dst = sb + hl * 16384 + px * 64 + ((c ^ ((px >> 1) & 3)) << 4);
        cp16(dst, src);
    }
    for (int i = tid; i < 3584; i += 512) {
        int hl = i & 1;
        int j  = i >> 1;
        int row = j >> 7;
        int r2  = j & 127;
        int px  = r2 >> 2;
        int c   = r2 & 3;
        int y = yq - 3 + row;
        if (y >= 0 && y < 32) {
            int rlin = row * 40 + px + 3;
            uint32_t dst = sb + CPK_KH + hl * 35840 + rlin * 64 +
                           ((c ^ ((rlin >> 1) & 3)) << 4);
            const __nv_bfloat16* src = (hl ? kl : kh) +
                ((size_t)img * HW + y * 32 + px) * 32 + c * 8;
            cp16(dst, src);
        }
    }
    {
        int hl  = tid >> 8;
        int r   = (tid >> 3) & 31;
        int chk = tid & 7;
        uint32_t dst = sb + (hl ? CPK_WL : CPK_WH) + r * 128 + ((chk ^ (r & 7)) << 4);
        cp16(dst, (hl ? wcl : wch) + r * 64 + chk * 8);
    }
    CP_COMMIT();
    CP_WAIT0();
    __syncthreads();

    const int yloc = w >> 1;
    const int x0   = (w & 1) * 16;

    uint32_t Ah[2][4], Al[2][4];
#pragma unroll
    for (int f = 0; f < 2; f++) {
        uint32_t r = w * 16 + (lane & 15);
        uint32_t c = f * 2 + (lane >> 4);
        uint32_t addr = sb + r * 64 + ((c ^ ((r >> 1) & 3)) << 4);
        LDSM4(Ah[f][0], Ah[f][1], Ah[f][2], Ah[f][3], addr);
        LDSM4(Al[f][0], Al[f][1], Al[f][2], Al[f][3], addr + 16384);
    }

    float* sbuf = (float*)(sm + CPK_SB + w * 1664);
    const uint32_t cs_hi = CPK_CS + w * 4096;
    const uint32_t cs_lo = cs_hi + 2048;
    const int lq = lane >> 2, lr = lane & 3;
    const int rr = lane >> 1;
    const int odd = lane & 1;

#pragma unroll 1
    for (int dy = 0; dy < 7; dy++) {
        const int row = yloc + dy;
        uint32_t Bh[3][4], Bl[3][4];
#pragma unroll
        for (int nt = 0; nt < 3; nt++) {
            uint32_t rlin = row * 40 + x0 + nt * 8 + (lane & 7);
            uint32_t c = lane >> 3;
            uint32_t addr = sb + CPK_KH + rlin * 64 + ((c ^ ((rlin >> 1) & 3)) << 4);
            LDSM4(Bh[nt][0], Bh[nt][1], Bh[nt][2], Bh[nt][3], addr);
            LDSM4(Bl[nt][0], Bl[nt][1], Bl[nt][2], Bl[nt][3], addr + 35840);
        }
        float acc[3][4];
#pragma unroll
        for (int nt = 0; nt < 3; nt++)
#pragma unroll
            for (int q = 0; q < 4; q++) acc[nt][q] = 0.f;

#pragma unroll
        for (int nt = 0; nt < 3; nt++) {
            MMA16816(acc[nt], Ah[0][0], Ah[0][1], Ah[0][2], Ah[0][3], Bh[nt][0], Bh[nt][1]);
            MMA16816(acc[nt], Ah[1][0], Ah[1][1], Ah[1][2], Ah[1][3], Bh[nt][2], Bh[nt][3]);
            MMA16816(acc[nt], Ah[0][0], Ah[0][1], Ah[0][2], Ah[0][3], Bl[nt][0], Bl[nt][1]);
            MMA16816(acc[nt], Ah[1][0], Ah[1][1], Ah[1][2], Ah[1][3], Bl[nt][2], Bl[nt][3]);
            MMA16816(acc[nt], Al[0][0], Al[0][1], Al[0][2], Al[0][3], Bh[nt][0], Bh[nt][1]);
            MMA16816(acc[nt], Al[1][0], Al[1][1], Al[1][2], Al[1][3], Bh[nt][2], Bh[nt][3]);
        }

        __syncwarp();
#pragma unroll
        for (int nt = 0; nt < 3; nt++) {
            *(float2*)&sbuf[lq * 26 + nt * 8 + lr * 2]       = make_float2(acc[nt][0], acc[nt][1]);
            *(float2*)&sbuf[(lq + 8) * 26 + nt * 8 + lr * 2] = make_float2(acc[nt][2], acc[nt][3]);
        }
        __syncwarp();

        {
            uint32_t coff = rr * 128 + ((dy ^ (rr & 7)) << 4) + odd * 8;
            if (!odd) {
                float s0 = sbuf[27 * rr + 0], s1 = sbuf[27 * rr + 1];
                float s2 = sbuf[27 * rr + 2], s3 = sbuf[27 * rr + 3];
                uint32_t h0, l0, h1, l1;
                split_bf16x2(s0, s1, h0, l0);
                split_bf16x2(s2, s3, h1, l1);
                *(uint2*)(sm + cs_hi + coff) = make_uint2(h0, h1);
                *(uint2*)(sm + cs_lo + coff) = make_uint2(l0, l1);
            } else {
                float s4 = sbuf[27 * rr + 4], s5 = sbuf[27 * rr + 5];
                float s6 = sbuf[27 * rr + 6];
                uint32_t h0, l0, h1, l1;
                split_bf16x2(s4, s5, h0, l0);
                split_bf16x2(s6, 0.f, h1, l1);
                *(uint2*)(sm + cs_hi + coff) = make_uint2(h0, h1);
                *(uint2*)(sm + cs_lo + coff) = make_uint2(l0, l1);
            }
        }
        __syncwarp();
    }

    {
        uint32_t coff = rr * 128 + ((7 ^ (rr & 7)) << 4) + odd * 8;
        uint2 z = make_uint2(0, 0);
        *(uint2*)(sm + cs_hi + coff) = z;
        *(uint2*)(sm + cs_lo + coff) = z;
    }
    __syncwarp();

    float pacc[4][4];
#pragma unroll
    for (int n = 0; n < 4; n++)
#pragma unroll
        for (int q = 0; q < 4; q++) pacc[n][q] = 0.f;

#pragma unroll
    for (int k = 0; k < 4; k++) {
        uint32_t bh[4][2], bl[4][2];
#pragma unroll
        for (int n = 0; n < 4; n++) {
            uint32_t wr = n * 8 + lq;
            uint32_t o0 = wr * 128 + (((2 * k)     ^ (wr & 7)) << 4) + lr * 4;
            uint32_t o1 = wr * 128 + (((2 * k + 1) ^ (wr & 7)) << 4) + lr * 4;
            bh[n][0] = *(const uint32_t*)(sm + CPK_WH + o0);
            bh[n][1] = *(const uint32_t*)(sm + CPK_WH + o1);
            bl[n][0] = *(const uint32_t*)(sm + CPK_WL + o0);
            bl[n][1] = *(const uint32_t*)(sm + CPK_WL + o1);
        }
        uint32_t r0 = lq, r1 = lq + 8;
        uint32_t a00 = r0 * 128 + (((2 * k)     ^ (r0 & 7)) << 4) + lr * 4;
        uint32_t a10 = r1 * 128 + (((2 * k)     ^ (r1 & 7)) << 4) + lr * 4;
        uint32_t a01 = r0 * 128 + (((2 * k + 1) ^ (r0 & 7)) << 4) + lr * 4;
        uint32_t a11 = r1 * 128 + (((2 * k + 1) ^ (r1 & 7)) << 4) + lr * 4;
        uint32_t Pa[4], Pl[4];
        Pa[0] = *(const uint32_t*)(sm + cs_hi + a00);
        Pa[1] = *(const uint32_t*)(sm + cs_hi + a10);
        Pa[2] = *(const uint32_t*)(sm + cs_hi + a01);
        Pa[3] = *(const uint32_t*)(sm + cs_hi + a11);
        Pl[0] = *(const uint32_t*)(sm + cs_lo + a00);
        Pl[1] = *(const uint32_t*)(sm + cs_lo + a10);
        Pl[2] = *(const uint32_t*)(sm + cs_lo + a01);
        Pl[3] = *(const uint32_t*)(sm + cs_lo + a11);
#pragma unroll
        for (int n = 0; n < 4; n++) {
            MMA16816(pacc[n], Pa[0], Pa[1], Pa[2], Pa[3], bh[n][0], bh[n][1]);
            MMA16816(pacc[n], Pl[0], Pl[1], Pl[2], Pl[3], bh[n][0], bh[n][1]);
            MMA16816(pacc[n], Pa[0], Pa[1], Pa[2], Pa[3], bl[n][0], bl[n][1]);
        }
    }

    const int b    = img >> 6;
    const int head = (img >> 3) & 7;
    const int t    = img & 7;
    const int y    = yq + yloc;
    const int p0   = y * 32 + x0 + lq;
#pragma unroll
    for (int n = 0; n < 4; n++) {
        int col = n * 8 + lr * 2;
        float b0 = bc[col], b1 = bc[col + 1];
        size_t row0 = (size_t)b * N_ + t * HW + p0;
        size_t g0 = row0 * C_ + head * 32 + col;
        size_t g1 = (row0 + 8) * C_ + head * 32 + col;
        uint32_t h0, l0, h1, l1;
        split_bf16x2(pacc[n][0] + b0, pacc[n][1] + b1, h0, l0);
        split_bf16x2(pacc[n][2] + b0, pacc[n][3] + b1, h1, l1);
        *(uint32_t*)(vhi + g0) = h0;
        *(uint32_t*)(vlo + g0) = l0;
        *(uint32_t*)(vhi + g1) = h1;
        *(uint32_t*)(vlo + g1) = l1;
    }
}

// =================================================================================
extern "C" void kernel_launch(void* const* d_in, const int* in_sizes, int n_in,
                              void* d_out, int out_size)
{
    const float* x      = (const float*)d_in[0];
    const float* w_qk   = (const float*)d_in[1];
    const float* w_corr = (const float*)d_in[2];
    const float* b_corr = (const float*)d_in[3];
    const float* w_proj = (const float*)d_in[4];
    const float* b_proj = (const float*)d_in[5];
    float* out = (float*)d_out;

    __nv_bfloat16 *qhp, *qlp, *khp, *klp, *vhi, *vlo;
    __nv_bfloat16 *wqh, *wql, *wph, *wpl, *wch, *wcl;
    cudaGetSymbolAddress((void**)&qhp, g_qh);
    cudaGetSymbolAddress((void**)&qlp, g_ql);
    cudaGetSymbolAddress((void**)&khp, g_kh);
    cudaGetSymbolAddress((void**)&klp, g_kl);
    cudaGetSymbolAddress((void**)&vhi, g_vhi);
    cudaGetSymbolAddress((void**)&vlo, g_vlo);
    cudaGetSymbolAddress((void**)&wqh, g_wqk_hi);
    cudaGetSymbolAddress((void**)&wql, g_wqk_lo);
    cudaGetSymbolAddress((void**)&wph, g_wpj_hi);
    cudaGetSymbolAddress((void**)&wpl, g_wpj_lo);
    cudaGetSymbolAddress((void**)&wch, g_wcT_hi);
    cudaGetSymbolAddress((void**)&wcl, g_wcT_lo);

    cudaFuncSetAttribute(gemm_qk,   cudaFuncAttributeMaxDynamicSharedMemorySize, GM_SMEM);
    cudaFuncSetAttribute(gemm_proj, cudaFuncAttributeMaxDynamicSharedMemorySize, GM_SMEM);
    cudaFuncSetAttribute(corr_proj, cudaFuncAttributeMaxDynamicSharedMemorySize, CPK_SMEM);

    // 0) weight hi/lo splits (tiny) — x split is now fused into gemm_qk
    conv_split<<<(512 * 256 / 4 + 255) / 256, 256>>>((const float4*)w_qk, (uint2*)wqh, (uint2*)wql, 512 * 256 / 4);
    conv_split<<<(256 * 256 / 4 + 255) / 256, 256>>>((const float4*)w_proj, (uint2*)wph, (uint2*)wpl, 256 * 256 / 4);
    prep_w<<<8, 256>>>(w_corr, wch, wcl);

    // 1) qk GEMM (fp32 A converted in-kernel) + normalize + shift -> q/k bf16 hi/lo
    gemm_qk<<<dim3(4, 512), 256, GM_SMEM>>>(x, wqh, wql, qhp, qlp, khp, klp);

    // 2) fused banded tensor-core correlation + projection -> v bf16 hi/lo
    corr_proj<<<BHT * 4, 512, CPK_SMEM>>>(qhp, qlp, khp, klp, wch, wcl, b_corr, vhi, vlo);

    // 3) out = v @ w_proj^T + b_proj
    gemm_proj<<<dim3(2, 512), 256, GM_SMEM>>>(vhi, vlo, wph, wpl, b_proj, out, 256);
}

// round 12
// speedup vs baseline: 1.0556x; 1.0556x over previous
#include <cuda_runtime.h>
#include <cuda_bf16.h>
#include <math.h>
#include <stdint.h>

#define B_    8
#define NH    8
#define T_    8
#define HD    32
#define C_    256
#define N_    8192
#define HW    1024
#define BHT   512            // B*NH*T
#define M_TOT 65536          // B*N

// ---------------- scratch (static device globals; no allocation) ----------------
__device__ __nv_bfloat16 g_qh[(size_t)BHT * HW * 32];  // q hi [img][px][ch]
__device__ __nv_bfloat16 g_ql[(size_t)BHT * HW * 32];
__device__ __nv_bfloat16 g_kh[(size_t)BHT * HW * 32];  // k hi (shifted) [img][px][ch]
__device__ __nv_bfloat16 g_kl[(size_t)BHT * HW * 32];
__device__ __nv_bfloat16 g_xhi[(size_t)M_TOT * C_];
__device__ __nv_bfloat16 g_xlo[(size_t)M_TOT * C_];
__device__ __nv_bfloat16 g_vhi[(size_t)M_TOT * C_];
__device__ __nv_bfloat16 g_vlo[(size_t)M_TOT * C_];
__device__ __nv_bfloat16 g_wqk_hi[512 * 256];
__device__ __nv_bfloat16 g_wqk_lo[512 * 256];
__device__ __nv_bfloat16 g_wpj_hi[256 * 256];
__device__ __nv_bfloat16 g_wpj_lo[256 * 256];
__device__ __nv_bfloat16 g_wcT_hi[32 * 64];            // w_corr [e][j'=dy*8+dx] padded
__device__ __nv_bfloat16 g_wcT_lo[32 * 64];

// ======================= asm helpers ==================
__device__ __forceinline__ uint32_t smem_u32(const void* p) {
    uint32_t a;
    asm("{ .reg .u64 t; cvta.to.shared.u64 t, %1; cvt.u32.u64 %0, t; }" : "=r"(a) : "l"(p));
    return a;
}
__device__ __forceinline__ void cp16(uint32_t saddr, const void* g) {
    asm volatile("cp.async.cg.shared.global [%0], [%1], 16;" :: "r"(saddr), "l"(g));
}
#define CP_COMMIT() asm volatile("cp.async.commit_group;" ::: "memory")
#define CP_WAIT1()  asm volatile("cp.async.wait_group 1;" ::: "memory")
#define CP_WAIT0()  asm volatile("cp.async.wait_group 0;" ::: "memory")

#define LDSM4(r0, r1, r2, r3, addr) \
    asm volatile("ldmatrix.sync.aligned.m8n8.x4.shared.b16 {%0,%1,%2,%3}, [%4];" \
                 : "=r"(r0), "=r"(r1), "=r"(r2), "=r"(r3) : "r"(addr))
#define MMA16816(c, a0, a1, a2, a3, b0, b1) \
    asm volatile("mma.sync.aligned.m16n8k16.row.col.f32.bf16.bf16.f32 " \
                 "{%0,%1,%2,%3},{%4,%5,%6,%7},{%8,%9},{%0,%1,%2,%3};" \
                 : "+f"((c)[0]), "+f"((c)[1]), "+f"((c)[2]), "+f"((c)[3]) \
                 : "r"(a0), "r"(a1), "r"(a2), "r"(a3), "r"(b0), "r"(b1))

__device__ __forceinline__ void split_bf16x2(float a, float b, uint32_t& hi, uint32_t& lo) {
    __nv_bfloat162 hb = __floats2bfloat162_rn(a, b);
    float r0 = a - __bfloat162float(__low2bfloat16(hb));
    float r1 = b - __bfloat162float(__high2bfloat16(hb));
    __nv_bfloat162 lb = __floats2bfloat162_rn(r0, r1);
    hi = *(uint32_t*)&hb;
    lo = *(uint32_t*)&lb;
}

// =================================================================================
__global__ void __launch_bounds__(256)
conv_split(const float4* __restrict__ in, uint2* __restrict__ hi,
           uint2* __restrict__ lo, int n4)
{
    int i = blockIdx.x * 256 + threadIdx.x;
    if (i >= n4) return;
    float4 f = in[i];
    uint32_t h0, l0, h1, l1;
    split_bf16x2(f.x, f.y, h0, l0);
    split_bf16x2(f.z, f.w, h1, l1);
    hi[i] = make_uint2(h0, h1);
    lo[i] = make_uint2(l0, l1);
}

// w_corr [32 e][49 j] -> padded [32 e][64 j'] with j' = dy*8+dx
__global__ void __launch_bounds__(256)
prep_w(const float* __restrict__ wc, __nv_bfloat16* __restrict__ wh,
       __nv_bfloat16* __restrict__ wl)
{
    int i = blockIdx.x * 256 + threadIdx.x;
    if (i >= 32 * 64) return;
    int e = i >> 6, jp = i & 63;
    int dy = jp >> 3, dx = jp & 7;
    float v = (dy < 7 && dx < 7) ? wc[e * 49 + dy * 7 + dx] : 0.f;
    __nv_bfloat16 h = __float2bfloat16(v);
    float r = v - __bfloat162float(h);
    wh[i] = h;
    wl[i] = __float2bfloat16(r);
}

// =================================================================================
// Shared GEMM machinery (proven): 128x128 block, 3-stage cp.async, K=256, 3-term.
// =================================================================================
#define KGEMM 256
#define NTILES 8
#define GM_STAGE 32768
#define GM_SMEM  (3 * GM_STAGE)

__device__ __forceinline__ void stage_load(
    uint32_t sbase, const __nv_bfloat16* __restrict__ Ahi,
    const __nv_bfloat16* __restrict__ Alo, const __nv_bfloat16* __restrict__ Bhi,
    const __nv_bfloat16* __restrict__ Blo, int m0, int n0, int kt, int tid)
{
    int t = tid * 2;
    int row = t >> 2;
    int cb  = t & 3;
#pragma unroll
    for (int j = 0; j < 2; j++) {
        int c16 = cb + j;
        uint32_t soff = (uint32_t)(row * 64 + ((c16 ^ ((row >> 1) & 3)) << 4));
        size_t ga = (size_t)row * KGEMM + kt * 32 + c16 * 8;
        cp16(sbase +     0 + soff, Ahi + (size_t)m0 * KGEMM + ga);
        cp16(sbase +  8192 + soff, Alo + (size_t)m0 * KGEMM + ga);
        cp16(sbase + 16384 + soff, Bhi + (size_t)n0 * KGEMM + ga);
        cp16(sbase + 24576 + soff, Blo + (size_t)n0 * KGEMM + ga);
    }
}

__device__ __forceinline__ void mma_ks_body(
    uint32_t aBase, uint32_t bBase, int ks, int lane, int wm, int wn,
    uint32_t bsel, float acc[4][4][4])
{
    const uint32_t l2 = lane & 15;
    uint32_t aaddr[4], baddr[4];
    {
        uint32_t achk = (uint32_t)(ks * 2) + (lane >> 4);
#pragma unroll
        for (int i = 0; i < 4; i++) {
            uint32_t r = wm + l2 + i * 16;
            aaddr[i] = aBase + r * 64 + ((achk ^ ((r >> 1) & 3)) << 4);
        }
        uint32_t bchk = (uint32_t)(ks * 2) + ((l2 >> 3) & 1);
#pragma unroll
        for (int j = 0; j < 4; j++) {
            uint32_t r = wn + (l2 & 7) + j * 8;
            baddr[j] = bBase + r * 64 + ((bchk ^ ((r >> 1) & 3)) << 4) + bsel;
        }
    }
    uint32_t a[4][4], al[4][4], b4[4][4];
#pragma unroll
    for (int i = 0; i < 4; i++) LDSM4(a[i][0], a[i][1], a[i][2], a[i][3], aaddr[i]);
#pragma unroll
    for (int j = 0; j < 4; j++) LDSM4(b4[j][0], b4[j][1], b4[j][2], b4[j][3], baddr[j]);
#pragma unroll
    for (int i = 0; i < 4; i++) LDSM4(al[i][0], al[i][1], al[i][2], al[i][3], aaddr[i] + 8192);
#pragma unroll
    for (int i = 0; i < 4; i++)
#pragma unroll
        for (int j = 0; j < 4; j++)
            MMA16816(acc[i][j], a[i][0], a[i][1], a[i][2], a[i][3], b4[j][0], b4[j][1]);
#pragma unroll
    for (int i = 0; i < 4; i++)
#pragma unroll
        for (int j = 0; j < 4; j++)
            MMA16816(acc[i][j], a[i][0], a[i][1], a[i][2], a[i][3], b4[j][2], b4[j][3]);
#pragma unroll
    for (int i = 0; i < 4; i++)
#pragma unroll
        for (int j = 0; j < 4; j++)
            MMA16816(acc[i][j], al[i][0], al[i][1], al[i][2], al[i][3], b4[j][0], b4[j][1]);
}

__device__ __forceinline__ void gemm_mainloop(
    const __nv_bfloat16* __restrict__ Ahi, const __nv_bfloat16* __restrict__ Alo,
    const __nv_bfloat16* __restrict__ Bhi, const __nv_bfloat16* __restrict__ Blo,
    uint32_t sb, int m0, int n0, int tid, int lane, int wm, int wn,
    float acc[4][4][4])
{
#pragma unroll
    for (int i = 0; i < 4; i++)
#pragma unroll
        for (int j = 0; j < 4; j++)
#pragma unroll
            for (int q = 0; q < 4; q++) acc[i][j][q] = 0.f;

    stage_load(sb,            Ahi, Alo, Bhi, Blo, m0, n0, 0, tid);
    CP_COMMIT();
    stage_load(sb + GM_STAGE, Ahi, Alo, Bhi, Blo, m0, n0, 1, tid);
    CP_COMMIT();

    const uint32_t bsel = (lane & 16) ? 8192u : 0u;

    int stage = 0;
    int lstage = 2;
    for (int kt = 0; kt < NTILES; kt++) {
        CP_WAIT1();
        __syncthreads();
        if (kt + 2 < NTILES)
            stage_load(sb + lstage * GM_STAGE, Ahi, Alo, Bhi, Blo, m0, n0, kt + 2, tid);
        CP_COMMIT();
        lstage = stage;

        const uint32_t sa = sb + stage * GM_STAGE;
        stage = (stage == 2) ? 0 : stage + 1;

#pragma unroll
        for (int ks = 0; ks < 2; ks++)
            mma_ks_body(sa, sa + 16384, ks, lane, wm, wn, bsel, acc);
    }
}

// =================================================================================
// GEMM1 fused (R10 proven): qk GEMM + L2-normalize + temporal shift; emits q/k
// as bf16 hi/lo in identical [img][px][ch] layout.
// =================================================================================
__global__ void __launch_bounds__(256, 2)
gemm_qk(const __nv_bfloat16* __restrict__ Ahi, const __nv_bfloat16* __restrict__ Alo,
        const __nv_bfloat16* __restrict__ Bhi, const __nv_bfloat16* __restrict__ Blo,
        __nv_bfloat16* __restrict__ qh, __nv_bfloat16* __restrict__ ql,
        __nv_bfloat16* __restrict__ kh, __nv_bfloat16* __restrict__ kl)
{
    const bool is_k = (blockIdx.x >= 2);
    const int tt_blk = (blockIdx.y >> 3) & 7;
    if (is_k && tt_blk == 0) return;        // dead k tile (shifted away)

    extern __shared__ char smg[];
    const uint32_t sb = smem_u32(smg);
    const int tid = threadIdx.x;
    const int lane = tid & 31;
    const int wid = tid >> 5;
    const int m0 = blockIdx.y * 128;
    const int n0 = blockIdx.x * 128;
    const int wm = (wid >> 2) * 64;
    const int wn = (wid & 3) * 32;

    float acc[4][4][4];
    gemm_mainloop(Ahi, Alo, Bhi, Blo, sb, m0, n0, tid, lane, wm, wn, acc);

    const int head = (((n0 & 255) + wn) >> 5);

#pragma unroll
    for (int i = 0; i < 4; i++) {
#pragma unroll
        for (int h = 0; h < 2; h++) {
            float v0[4], v1[4];
            float ss = 0.f;
#pragma unroll
            for (int j = 0; j < 4; j++) {
                v0[j] = acc[i][j][2 * h];
                v1[j] = acc[i][j][2 * h + 1];
                ss += v0[j] * v0[j] + v1[j] * v1[j];
            }
            ss += __shfl_xor_sync(0xffffffffu, ss, 1);
            ss += __shfl_xor_sync(0xffffffffu, ss, 2);
            float inv = 1.0f / fmaxf(sqrtf(ss), 1e-12f);

            int r = m0 + wm + i * 16 + (lane >> 2) + h * 8;
            int b  = r >> 13;
            int tt = (r >> 10) & 7;
            int p  = r & 1023;

            uint32_t hw[4], lw[4];
#pragma unroll
            for (int j = 0; j < 4; j++)
                split_bf16x2(v0[j] * inv, v1[j] * inv, hw[j], lw[j]);

            if (!is_k) {
                size_t base = ((size_t)(b * 64 + head * 8 + tt) * HW + p) * 32;
#pragma unroll
                for (int j = 0; j < 4; j++) {
                    int col = j * 8 + (lane & 3) * 2;
                    *(uint32_t*)(qh + base + col) = hw[j];
                    *(uint32_t*)(ql + base + col) = lw[j];
                }
            } else {
                if (tt >= 1) {
                    size_t base = ((size_t)(b * 64 + head * 8 + (tt - 1)) * HW + p) * 32;
#pragma unroll
                    for (int j = 0; j < 4; j++) {
                        int col = j * 8 + (lane & 3) * 2;
                        *(uint32_t*)(kh + base + col) = hw[j];
                        *(uint32_t*)(kl + base + col) = lw[j];
                    }
                }
                if (tt == 7) {
                    size_t base = ((size_t)(b * 64 + head * 8 + 7) * HW + p) * 32;
#pragma unroll
                    for (int j = 0; j < 4; j++) {
                        int col = j * 8 + (lane & 3) * 2;
                        *(uint32_t*)(kh + base + col) = hw[j];
                        *(uint32_t*)(kl + base + col) = lw[j];
                    }
                }
            }
        }
    }
}

// =================================================================================
// GEMM4: out = v @ w_proj^T + bias, fp32 out (unchanged proven path)
// =================================================================================
__global__ void __launch_bounds__(256, 2)
gemm_proj(const __nv_bfloat16* __restrict__ Ahi, const __nv_bfloat16* __restrict__ Alo,
          const __nv_bfloat16* __restrict__ Bhi, const __nv_bfloat16* __restrict__ Blo,
          const float* __restrict__ bias, float* __restrict__ C, int ldc)
{
    extern __shared__ char smg[];
    const uint32_t sb = smem_u32(smg);
    const int tid = threadIdx.x;
    const int lane = tid & 31;
    const int wid = tid >> 5;
    const int m0 = blockIdx.y * 128;
    const int n0 = blockIdx.x * 128;
    const int wm = (wid >> 2) * 64;
    const int wn = (wid & 3) * 32;

    float acc[4][4][4];
    gemm_mainloop(Ahi, Alo, Bhi, Blo, sb, m0, n0, tid, lane, wm, wn, acc);

#pragma unroll
    for (int j = 0; j < 4; j++) {
        int c = n0 + wn + j * 8 + (lane & 3) * 2;
        float b0 = bias[c], b1 = bias[c + 1];
#pragma unroll
        for (int i = 0; i < 4; i++) {
            int r = m0 + wm + i * 16 + (lane >> 2);
            *(float2*)(C + (size_t)r * ldc + c) =
                make_float2(acc[i][j][0] + b0, acc[i][j][1] + b1);
            *(float2*)(C + (size_t)(r + 8) * ldc + c) =
                make_float2(acc[i][j][2] + b0, acc[i][j][3] + b1);
        }
    }
}

// =================================================================================
// corr_proj v2: 4 y-rows per block, 8 warps (256 thr), 2 CTAs/SM.
// smem (108544 B total):
//   q hi 0 / lo 8192 (128 px x 64B each)       [reused as sbuf after A-frag load]
//   k hi 16384 / lo 41984 (25600 each: 10 rows x 40 px x 64B, swizzled)
//   w hi 67584 / lo 71680 (4KB each)
//   corr buf 75776 + w*4096 (per warp: hi 2KB + lo 2KB)
//   sbuf (overlay on q region): 0 + w*1664 (per warp fp32 staging, 8*1664=13312)
// =================================================================================
#define CPK_KH 16384u
#define CPK_KL 41984u
#define CPK_WH 67584u
#define CPK_WL 71680u
#define CPK_CS 75776u
#define CPK_SMEM 108544

__global__ void __launch_bounds__(256, 2)
corr_proj(const __nv_bfloat16* __restrict__ qh, const __nv_bfloat16* __restrict__ ql,
          const __nv_bfloat16* __restrict__ kh, const __nv_bfloat16* __restrict__ kl,
          const __nv_bfloat16* __restrict__ wch, const __nv_bfloat16* __restrict__ wcl,
          const float* __restrict__ bc,
          __nv_bfloat16* __restrict__ vhi, __nv_bfloat16* __restrict__ vlo)
{
    extern __shared__ char sm[];
    const uint32_t sb = smem_u32(sm);
    const int tid  = threadIdx.x;
    const int lane = tid & 31;
    const int w    = tid >> 5;           // warp = segment 0..7
    const int img  = blockIdx.x >> 3;
    const int yq   = (blockIdx.x & 7) * 4;

    // zero whole k region (hi+lo: 51200 B = 3200 uint4)
    for (int i = tid; i < 3200; i += 256)
        ((uint4*)(sm + CPK_KH))[i] = make_uint4(0, 0, 0, 0);
    __syncthreads();

    // q fill: 128 px x 4 chunks x {hi,lo} = 1024 cp16
    for (int i = tid; i < 1024; i += 256) {
        int hl = i >> 9;
        int px = (i >> 2) & 127;
        int c  = i & 3;
        const __nv_bfloat16* src = (hl ? ql : qh) +
            ((size_t)img * HW + yq * 32 + px) * 32 + c * 8;
        uint32_t dst = sb + hl * 8192 + px * 64 + ((c ^ ((px >> 1) & 3)) << 4);
        cp16(dst, src);
    }
    // k fill: 10 rows x 32 px x 4 chunks x {hi,lo} = 2560 cp16 (valid rows only)
    for (int i = tid; i < 2560; i += 256) {
        int hl = i & 1;
        int j  = i >> 1;              // 0..1279
        int row = j >> 7;             // 0..9
        int r2  = j & 127;
        int px  = r2 >> 2;
        int c   = r2 & 3;
        int y = yq - 3 + row;
        if (y >= 0 && y < 32) {
            int rlin = row * 40 + px + 3;
            uint32_t dst = sb + (hl ? CPK_KL : CPK_KH) + rlin * 64 +
                           ((c ^ ((rlin >> 1) & 3)) << 4);
            const __nv_bfloat16* src = (hl ? kl : kh) +
                ((size_t)img * HW + y * 32 + px) * 32 + c * 8;
            cp16(dst, src);
        }
    }
    // w fill: 32 rows x 8 chunks x {hi,lo} = 512 cp16 (2 per thread)
    for (int i = tid; i < 512; i += 256) {
        int hl  = i >> 8;
        int r   = (i >> 3) & 31;
        int chk = i & 7;
        uint32_t dst = sb + (hl ? CPK_WL : CPK_WH) + r * 128 + ((chk ^ (r & 7)) << 4);
        cp16(dst, (hl ? wcl : wch) + r * 64 + chk * 8);
    }
    CP_COMMIT();
    CP_WAIT0();
    __syncthreads();

    const int yloc = w >> 1;            // 0..3
    const int x0   = (w & 1) * 16;

    // A fragments (q, reused across all dy): 2 k16 chunks, hi+lo
    uint32_t Ah[2][4], Al[2][4];
#pragma unroll
    for (int f = 0; f < 2; f++) {
        uint32_t r = w * 16 + (lane & 15);
        uint32_t c = f * 2 + (lane >> 4);
        uint32_t addr = sb + r * 64 + ((c ^ ((r >> 1) & 3)) << 4);
        LDSM4(Ah[f][0], Ah[f][1], Ah[f][2], Ah[f][3], addr);
        LDSM4(Al[f][0], Al[f][1], Al[f][2], Al[f][3], addr + 8192);
    }
    __syncthreads();   // q region now dead -> reused as sbuf

    float* sbuf = (float*)(sm + w * 1664);        // [16][26], band-read stride 27
    const uint32_t cs_hi = CPK_CS + w * 4096;
    const uint32_t cs_lo = cs_hi + 2048;
    const int lq = lane >> 2, lr = lane & 3;
    const int rr = lane >> 1;                      // band row 0..15
    const int odd = lane & 1;

#pragma unroll 1
    for (int dy = 0; dy < 7; dy++) {
        const int row = yloc + dy;                 // 0..9
        uint32_t Bh[3][4], Bl[3][4];
#pragma unroll
        for (int nt = 0; nt < 3; nt++) {
            uint32_t rlin = row * 40 + x0 + nt * 8 + (lane & 7);
            uint32_t c = lane >> 3;
            uint32_t addr = sb + CPK_KH + rlin * 64 + ((c ^ ((rlin >> 1) & 3)) << 4);
            LDSM4(Bh[nt][0], Bh[nt][1], Bh[nt][2], Bh[nt][3], addr);
            LDSM4(Bl[nt][0], Bl[nt][1], Bl[nt][2], Bl[nt][3], addr + 25600);
        }
        float acc[3][4];
#pragma unroll
        for (int nt = 0; nt < 3; nt++)
#pragma unroll
            for (int q = 0; q < 4; q++) acc[nt][q] = 0.f;

#pragma unroll
        for (int nt = 0; nt < 3; nt++) {
            MMA16816(acc[nt], Ah[0][0], Ah[0][1], Ah[0][2], Ah[0][3], Bh[nt][0], Bh[nt][1]);
            MMA16816(acc[nt], Ah[1][0], Ah[1][1], Ah[1][2], Ah[1][3], Bh[nt][2], Bh[nt][3]);
            MMA16816(acc[nt], Ah[0][0], Ah[0][1], Ah[0][2], Ah[0][3], Bl[nt][0], Bl[nt][1]);
            MMA16816(acc[nt], Ah[1][0], Ah[1][1], Ah[1][2], Ah[1][3], Bl[nt][2], Bl[nt][3]);
            MMA16816(acc[nt], Al[0][0], Al[0][1], Al[0][2], Al[0][3], Bh[nt][0], Bh[nt][1]);
            MMA16816(acc[nt], Al[1][0], Al[1][1], Al[1][2], Al[1][3], Bh[nt][2], Bh[nt][3]);
        }

        __syncwarp();
#pragma unroll
        for (int nt = 0; nt < 3; nt++) {
            *(float2*)&sbuf[lq * 26 + nt * 8 + lr * 2]       = make_float2(acc[nt][0], acc[nt][1]);
            *(float2*)&sbuf[(lq + 8) * 26 + nt * 8 + lr * 2] = make_float2(acc[nt][2], acc[nt][3]);
        }
        __syncwarp();

        {
            uint32_t coff = rr * 128 + ((dy ^ (rr & 7)) << 4) + odd * 8;
            if (!odd) {
                float s0 = sbuf[27 * rr + 0], s1 = sbuf[27 * rr + 1];
                float s2 = sbuf[27 * rr + 2], s3 = sbuf[27 * rr + 3];
                uint32_t h0, l0, h1, l1;
                split_bf16x2(s0, s1, h0, l0);
                split_bf16x2(s2, s3, h1, l1);
                *(uint2*)(sm + cs_hi + coff) = make_uint2(h0, h1);
                *(uint2*)(sm + cs_lo + coff) = make_uint2(l0, l1);
            } else {
                float s4 = sbuf[27 * rr + 4], s5 = sbuf[27 * rr + 5];
                float s6 = sbuf[27 * rr + 6];
                uint32_t h0, l0, h1, l1;
                split_bf16x2(s4, s5, h0, l0);
                split_bf16x2(s6, 0.f, h1, l1);
                *(uint2*)(sm + cs_hi + coff) = make_uint2(h0, h1);
                *(uint2*)(sm + cs_lo + coff) = make_uint2(l0, l1);
            }
        }
        __syncwarp();
    }

    // zero tail chunk j' = 56..63
    {
        uint32_t coff = rr * 128 + ((7 ^ (rr & 7)) << 4) + odd * 8;
        uint2 z = make_uint2(0, 0);
        *(uint2*)(sm + cs_hi + coff) = z;
        *(uint2*)(sm + cs_lo + coff) = z;
    }
    __syncwarp();

    // ---------- Phase 2: projection m16 x n32 x k64, 3-term ----------
    float pacc[4][4];
#pragma unroll
    for (int n = 0; n < 4; n++)
#pragma unroll
        for (int q = 0; q < 4; q++) pacc[n][q] = 0.f;

#pragma unroll
    for (int k = 0; k < 4; k++) {
        uint32_t bh[4][2], bl[4][2];
#pragma unroll
        for (int n = 0; n < 4; n++) {
            uint32_t wr = n * 8 + lq;
            uint32_t o0 = wr * 128 + (((2 * k)     ^ (wr & 7)) << 4) + lr * 4;
            uint32_t o1 = wr * 128 + (((2 * k + 1) ^ (wr & 7)) << 4) + lr * 4;
            bh[n][0] = *(const uint32_t*)(sm + CPK_WH + o0);
            bh[n][1] = *(const uint32_t*)(sm + CPK_WH + o1);
            bl[n][0] = *(const uint32_t*)(sm + CPK_WL + o0);
            bl[n][1] = *(const uint32_t*)(sm + CPK_WL + o1);
        }
        uint32_t r0 = lq, r1 = lq + 8;
        uint32_t a00 = r0 * 128 + (((2 * k)     ^ (r0 & 7)) << 4) + lr * 4;
        uint32_t a10 = r1 * 128 + (((2 * k)     ^ (r1 & 7)) << 4) + lr * 4;
        uint32_t a01 = r0 * 128 + (((2 * k + 1) ^ (r0 & 7)) << 4) + lr * 4;
        uint32_t a11 = r1 * 128 + (((2 * k + 1) ^ (r1 & 7)) << 4) + lr * 4;
        uint32_t Pa[4], Pl[4];
        Pa[0] = *(const uint32_t*)(sm + cs_hi + a00);
        Pa[1] = *(const uint32_t*)(sm + cs_hi + a10);
        Pa[2] = *(const uint32_t*)(sm + cs_hi + a01);
        Pa[3] = *(const uint32_t*)(sm + cs_hi + a11);
        Pl[0] = *(const uint32_t*)(sm + cs_lo + a00);
        Pl[1] = *(const uint32_t*)(sm + cs_lo + a10);
        Pl[2] = *(const uint32_t*)(sm + cs_lo + a01);
        Pl[3] = *(const uint32_t*)(sm + cs_lo + a11);
#pragma unroll
        for (int n = 0; n < 4; n++) {
            MMA16816(pacc[n], Pa[0], Pa[1], Pa[2], Pa[3], bh[n][0], bh[n][1]);
            MMA16816(pacc[n], Pl[0], Pl[1], Pl[2], Pl[3], bh[n][0], bh[n][1]);
            MMA16816(pacc[n], Pa[0], Pa[1], Pa[2], Pa[3], bl[n][0], bl[n][1]);
        }
    }

    // epilogue: v + b_corr, split hi/lo, store
    const int b    = img >> 6;
    const int head = (img >> 3) & 7;
    const int t    = img & 7;
    const int y    = yq + yloc;
    const int p0   = y * 32 + x0 + lq;
#pragma unroll
    for (int n = 0; n < 4; n++) {
        int col = n * 8 + lr * 2;
        float b0 = bc[col], b1 = bc[col + 1];
        size_t row0 = (size_t)b * N_ + t * HW + p0;
        size_t g0 = row0 * C_ + head * 32 + col;
        size_t g1 = (row0 + 8) * C_ + head * 32 + col;
        uint32_t h0, l0, h1, l1;
        split_bf16x2(pacc[n][0] + b0, pacc[n][1] + b1, h0, l0);
        split_bf16x2(pacc[n][2] + b0, pacc[n][3] + b1, h1, l1);
        *(uint32_t*)(vhi + g0) = h0;
        *(uint32_t*)(vlo + g0) = l0;
        *(uint32_t*)(vhi + g1) = h1;
        *(uint32_t*)(vlo + g1) = l1;
    }
}

// =================================================================================
extern "C" void kernel_launch(void* const* d_in, const int* in_sizes, int n_in,
                              void* d_out, int out_size)
{
    const float* x      = (const float*)d_in[0];
    const float* w_qk   = (const float*)d_in[1];
    const float* w_corr = (const float*)d_in[2];
    const float* b_corr = (const float*)d_in[3];
    const float* w_proj = (const float*)d_in[4];
    const float* b_proj = (const float*)d_in[5];
    float* out = (float*)d_out;

    __nv_bfloat16 *qhp, *qlp, *khp, *klp, *xhi, *xlo, *vhi, *vlo;
    __nv_bfloat16 *wqh, *wql, *wph, *wpl, *wch, *wcl;
    cudaGetSymbolAddress((void**)&qhp, g_qh);
    cudaGetSymbolAddress((void**)&qlp, g_ql);
    cudaGetSymbolAddress((void**)&khp, g_kh);
    cudaGetSymbolAddress((void**)&klp, g_kl);
    cudaGetSymbolAddress((void**)&xhi, g_xhi);
    cudaGetSymbolAddress((void**)&xlo, g_xlo);
    cudaGetSymbolAddress((void**)&vhi, g_vhi);
    cudaGetSymbolAddress((void**)&vlo, g_vlo);
    cudaGetSymbolAddress((void**)&wqh, g_wqk_hi);
    cudaGetSymbolAddress((void**)&wql, g_wqk_lo);
    cudaGetSymbolAddress((void**)&wph, g_wpj_hi);
    cudaGetSymbolAddress((void**)&wpl, g_wpj_lo);
    cudaGetSymbolAddress((void**)&wch, g_wcT_hi);
    cudaGetSymbolAddress((void**)&wcl, g_wcT_lo);

    cudaFuncSetAttribute(gemm_qk,   cudaFuncAttributeMaxDynamicSharedMemorySize, GM_SMEM);
    cudaFuncSetAttribute(gemm_proj, cudaFuncAttributeMaxDynamicSharedMemorySize, GM_SMEM);
    cudaFuncSetAttribute(corr_proj, cudaFuncAttributeMaxDynamicSharedMemorySize, CPK_SMEM);

    // 0) hi/lo splits + w_corr prep
    conv_split<<<(M_TOT * C_ / 4 + 255) / 256, 256>>>((const float4*)x, (uint2*)xhi, (uint2*)xlo, M_TOT * C_ / 4);
    conv_split<<<(512 * 256 / 4 + 255) / 256, 256>>>((const float4*)w_qk, (uint2*)wqh, (uint2*)wql, 512 * 256 / 4);
    conv_split<<<(256 * 256 / 4 + 255) / 256, 256>>>((const float4*)w_proj, (uint2*)wph, (uint2*)wpl, 256 * 256 / 4);
    prep_w<<<8, 256>>>(w_corr, wch, wcl);

    // 1) qk GEMM fused with normalize + temporal shift -> q/k bf16 hi/lo
    gemm_qk<<<dim3(4, 512), 256, GM_SMEM>>>(xhi, xlo, wqh, wql, qhp, qlp, khp, klp);

    // 2) fused banded tensor-core correlation + projection (2 CTAs/SM) -> v hi/lo
    corr_proj<<<BHT * 8, 256, CPK_SMEM>>>(qhp, qlp, khp, klp, wch, wcl, b_corr, vhi, vlo);

    // 3) out = v @ w_proj^T + b_proj
    gemm_proj<<<dim3(2, 512), 256, GM_SMEM>>>(vhi, vlo, wph, wpl, b_proj, out, 256);
}

// round 13
// speedup vs baseline: 1.2036x; 1.1401x over previous
#include <cuda_runtime.h>
#include <cuda_bf16.h>
#include <cuda_fp16.h>
#include <math.h>
#include <stdint.h>

#define B_    8
#define NH    8
#define T_    8
#define HD    32
#define C_    256
#define N_    8192
#define HW    1024
#define BHT   512            // B*NH*T
#define M_TOT 65536          // B*N

// ---------------- scratch (static device globals; no allocation) ----------------
__device__ __half g_qh[(size_t)BHT * HW * 32];         // q fp16 [img][px][ch]
__device__ __half g_kh[(size_t)BHT * HW * 32];         // k fp16 (shifted) [img][px][ch]
__device__ __nv_bfloat16 g_xhi[(size_t)M_TOT * C_];
__device__ __nv_bfloat16 g_xlo[(size_t)M_TOT * C_];
__device__ __nv_bfloat16 g_vhi[(size_t)M_TOT * C_];
__device__ __nv_bfloat16 g_vlo[(size_t)M_TOT * C_];
__device__ __nv_bfloat16 g_wqk_hi[512 * 256];
__device__ __nv_bfloat16 g_wqk_lo[512 * 256];
__device__ __nv_bfloat16 g_wpj_hi[256 * 256];
__device__ __nv_bfloat16 g_wpj_lo[256 * 256];
__device__ __half g_wcT[32 * 64];                      // w_corr fp16 [e][j'=dy*8+dx]

// ======================= asm helpers ==================
__device__ __forceinline__ uint32_t smem_u32(const void* p) {
    uint32_t a;
    asm("{ .reg .u64 t; cvta.to.shared.u64 t, %1; cvt.u32.u64 %0, t; }" : "=r"(a) : "l"(p));
    return a;
}
__device__ __forceinline__ void cp16(uint32_t saddr, const void* g) {
    asm volatile("cp.async.cg.shared.global [%0], [%1], 16;" :: "r"(saddr), "l"(g));
}
#define CP_COMMIT() asm volatile("cp.async.commit_group;" ::: "memory")
#define CP_WAIT1()  asm volatile("cp.async.wait_group 1;" ::: "memory")
#define CP_WAIT0()  asm volatile("cp.async.wait_group 0;" ::: "memory")

#define LDSM4(r0, r1, r2, r3, addr) \
    asm volatile("ldmatrix.sync.aligned.m8n8.x4.shared.b16 {%0,%1,%2,%3}, [%4];" \
                 : "=r"(r0), "=r"(r1), "=r"(r2), "=r"(r3) : "r"(addr))
// bf16 mma (GEMM path)
#define MMA16816(c, a0, a1, a2, a3, b0, b1) \
    asm volatile("mma.sync.aligned.m16n8k16.row.col.f32.bf16.bf16.f32 " \
                 "{%0,%1,%2,%3},{%4,%5,%6,%7},{%8,%9},{%0,%1,%2,%3};" \
                 : "+f"((c)[0]), "+f"((c)[1]), "+f"((c)[2]), "+f"((c)[3]) \
                 : "r"(a0), "r"(a1), "r"(a2), "r"(a3), "r"(b0), "r"(b1))
// fp16 mma (corr path)
#define MMA16816H(c, a0, a1, a2, a3, b0, b1) \
    asm volatile("mma.sync.aligned.m16n8k16.row.col.f32.f16.f16.f32 " \
                 "{%0,%1,%2,%3},{%4,%5,%6,%7},{%8,%9},{%0,%1,%2,%3};" \
                 : "+f"((c)[0]), "+f"((c)[1]), "+f"((c)[2]), "+f"((c)[3]) \
                 : "r"(a0), "r"(a1), "r"(a2), "r"(a3), "r"(b0), "r"(b1))

__device__ __forceinline__ void split_bf16x2(float a, float b, uint32_t& hi, uint32_t& lo) {
    __nv_bfloat162 hb = __floats2bfloat162_rn(a, b);
    float r0 = a - __bfloat162float(__low2bfloat16(hb));
    float r1 = b - __bfloat162float(__high2bfloat16(hb));
    __nv_bfloat162 lb = __floats2bfloat162_rn(r0, r1);
    hi = *(uint32_t*)&hb;
    lo = *(uint32_t*)&lb;
}
__device__ __forceinline__ uint32_t h2u(float a, float b) {
    __half2 h = __floats2half2_rn(a, b);
    return *(uint32_t*)&h;
}

// =================================================================================
__global__ void __launch_bounds__(256)
conv_split(const float4* __restrict__ in, uint2* __restrict__ hi,
           uint2* __restrict__ lo, int n4)
{
    int i = blockIdx.x * 256 + threadIdx.x;
    if (i >= n4) return;
    float4 f = in[i];
    uint32_t h0, l0, h1, l1;
    split_bf16x2(f.x, f.y, h0, l0);
    split_bf16x2(f.z, f.w, h1, l1);
    hi[i] = make_uint2(h0, h1);
    lo[i] = make_uint2(l0, l1);
}

// w_corr [32 e][49 j] -> padded fp16 [32 e][64 j'] with j' = dy*8+dx
__global__ void __launch_bounds__(256)
prep_w(const float* __restrict__ wc, __half* __restrict__ wh)
{
    int i = blockIdx.x * 256 + threadIdx.x;
    if (i >= 32 * 64) return;
    int e = i >> 6, jp = i & 63;
    int dy = jp >> 3, dx = jp & 7;
    float v = (dy < 7 && dx < 7) ? wc[e * 49 + dy * 7 + dx] : 0.f;
    wh[i] = __float2half(v);
}

// =================================================================================
// Shared GEMM machinery (proven): 128x128 block, 3-stage cp.async, K=256, 3-term.
// =================================================================================
#define KGEMM 256
#define NTILES 8
#define GM_STAGE 32768
#define GM_SMEM  (3 * GM_STAGE)

__device__ __forceinline__ void stage_load(
    uint32_t sbase, const __nv_bfloat16* __restrict__ Ahi,
    const __nv_bfloat16* __restrict__ Alo, const __nv_bfloat16* __restrict__ Bhi,
    const __nv_bfloat16* __restrict__ Blo, int m0, int n0, int kt, int tid)
{
    int t = tid * 2;
    int row = t >> 2;
    int cb  = t & 3;
#pragma unroll
    for (int j = 0; j < 2; j++) {
        int c16 = cb + j;
        uint32_t soff = (uint32_t)(row * 64 + ((c16 ^ ((row >> 1) & 3)) << 4));
        size_t ga = (size_t)row * KGEMM + kt * 32 + c16 * 8;
        cp16(sbase +     0 + soff, Ahi + (size_t)m0 * KGEMM + ga);
        cp16(sbase +  8192 + soff, Alo + (size_t)m0 * KGEMM + ga);
        cp16(sbase + 16384 + soff, Bhi + (size_t)n0 * KGEMM + ga);
        cp16(sbase + 24576 + soff, Blo + (size_t)n0 * KGEMM + ga);
    }
}

__device__ __forceinline__ void mma_ks_body(
    uint32_t aBase, uint32_t bBase, int ks, int lane, int wm, int wn,
    uint32_t bsel, float acc[4][4][4])
{
    const uint32_t l2 = lane & 15;
    uint32_t aaddr[4], baddr[4];
    {
        uint32_t achk = (uint32_t)(ks * 2) + (lane >> 4);
#pragma unroll
        for (int i = 0; i < 4; i++) {
            uint32_t r = wm + l2 + i * 16;
            aaddr[i] = aBase + r * 64 + ((achk ^ ((r >> 1) & 3)) << 4);
        }
        uint32_t bchk = (uint32_t)(ks * 2) + ((l2 >> 3) & 1);
#pragma unroll
        for (int j = 0; j < 4; j++) {
            uint32_t r = wn + (l2 & 7) + j * 8;
            baddr[j] = bBase + r * 64 + ((bchk ^ ((r >> 1) & 3)) << 4) + bsel;
        }
    }
    uint32_t a[4][4], al[4][4], b4[4][4];
#pragma unroll
    for (int i = 0; i < 4; i++) LDSM4(a[i][0], a[i][1], a[i][2], a[i][3], aaddr[i]);
#pragma unroll
    for (int j = 0; j < 4; j++) LDSM4(b4[j][0], b4[j][1], b4[j][2], b4[j][3], baddr[j]);
#pragma unroll
    for (int i = 0; i < 4; i++) LDSM4(al[i][0], al[i][1], al[i][2], al[i][3], aaddr[i] + 8192);
#pragma unroll
    for (int i = 0; i < 4; i++)
#pragma unroll
        for (int j = 0; j < 4; j++)
            MMA16816(acc[i][j], a[i][0], a[i][1], a[i][2], a[i][3], b4[j][0], b4[j][1]);
#pragma unroll
    for (int i = 0; i < 4; i++)
#pragma unroll
        for (int j = 0; j < 4; j++)
            MMA16816(acc[i][j], a[i][0], a[i][1], a[i][2], a[i][3], b4[j][2], b4[j][3]);
#pragma unroll
    for (int i = 0; i < 4; i++)
#pragma unroll
        for (int j = 0; j < 4; j++)
            MMA16816(acc[i][j], al[i][0], al[i][1], al[i][2], al[i][3], b4[j][0], b4[j][1]);
}

__device__ __forceinline__ void gemm_mainloop(
    const __nv_bfloat16* __restrict__ Ahi, const __nv_bfloat16* __restrict__ Alo,
    const __nv_bfloat16* __restrict__ Bhi, const __nv_bfloat16* __restrict__ Blo,
    uint32_t sb, int m0, int n0, int tid, int lane, int wm, int wn,
    float acc[4][4][4])
{
#pragma unroll
    for (int i = 0; i < 4; i++)
#pragma unroll
        for (int j = 0; j < 4; j++)
#pragma unroll
            for (int q = 0; q < 4; q++) acc[i][j][q] = 0.f;

    stage_load(sb,            Ahi, Alo, Bhi, Blo, m0, n0, 0, tid);
    CP_COMMIT();
    stage_load(sb + GM_STAGE, Ahi, Alo, Bhi, Blo, m0, n0, 1, tid);
    CP_COMMIT();

    const uint32_t bsel = (lane & 16) ? 8192u : 0u;

    int stage = 0;
    int lstage = 2;
    for (int kt = 0; kt < NTILES; kt++) {
        CP_WAIT1();
        __syncthreads();
        if (kt + 2 < NTILES)
            stage_load(sb + lstage * GM_STAGE, Ahi, Alo, Bhi, Blo, m0, n0, kt + 2, tid);
        CP_COMMIT();
        lstage = stage;

        const uint32_t sa = sb + stage * GM_STAGE;
        stage = (stage == 2) ? 0 : stage + 1;

#pragma unroll
        for (int ks = 0; ks < 2; ks++)
            mma_ks_body(sa, sa + 16384, ks, lane, wm, wn, bsel, acc);
    }
}

// =================================================================================
// GEMM1 fused: qk GEMM + L2-normalize + temporal shift; emits q/k as fp16 single
// in [img][px][ch] layout.
// =================================================================================
__global__ void __launch_bounds__(256, 2)
gemm_qk(const __nv_bfloat16* __restrict__ Ahi, const __nv_bfloat16* __restrict__ Alo,
        const __nv_bfloat16* __restrict__ Bhi, const __nv_bfloat16* __restrict__ Blo,
        __half* __restrict__ qh, __half* __restrict__ kh)
{
    const bool is_k = (blockIdx.x >= 2);
    const int tt_blk = (blockIdx.y >> 3) & 7;
    if (is_k && tt_blk == 0) return;        // dead k tile (shifted away)

    extern __shared__ char smg[];
    const uint32_t sb = smem_u32(smg);
    const int tid = threadIdx.x;
    const int lane = tid & 31;
    const int wid = tid >> 5;
    const int m0 = blockIdx.y * 128;
    const int n0 = blockIdx.x * 128;
    const int wm = (wid >> 2) * 64;
    const int wn = (wid & 3) * 32;

    float acc[4][4][4];
    gemm_mainloop(Ahi, Alo, Bhi, Blo, sb, m0, n0, tid, lane, wm, wn, acc);

    const int head = (((n0 & 255) + wn) >> 5);

#pragma unroll
    for (int i = 0; i < 4; i++) {
#pragma unroll
        for (int h = 0; h < 2; h++) {
            float v0[4], v1[4];
            float ss = 0.f;
#pragma unroll
            for (int j = 0; j < 4; j++) {
                v0[j] = acc[i][j][2 * h];
                v1[j] = acc[i][j][2 * h + 1];
                ss += v0[j] * v0[j] + v1[j] * v1[j];
            }
            ss += __shfl_xor_sync(0xffffffffu, ss, 1);
            ss += __shfl_xor_sync(0xffffffffu, ss, 2);
            float inv = 1.0f / fmaxf(sqrtf(ss), 1e-12f);

            int r = m0 + wm + i * 16 + (lane >> 2) + h * 8;
            int b  = r >> 13;
            int tt = (r >> 10) & 7;
            int p  = r & 1023;

            uint32_t hw[4];
#pragma unroll
            for (int j = 0; j < 4; j++) hw[j] = h2u(v0[j] * inv, v1[j] * inv);

            if (!is_k) {
                size_t base = ((size_t)(b * 64 + head * 8 + tt) * HW + p) * 32;
#pragma unroll
                for (int j = 0; j < 4; j++) {
                    int col = j * 8 + (lane & 3) * 2;
                    *(uint32_t*)(qh + base + col) = hw[j];
                }
            } else {
                if (tt >= 1) {
                    size_t base = ((size_t)(b * 64 + head * 8 + (tt - 1)) * HW + p) * 32;
#pragma unroll
                    for (int j = 0; j < 4; j++) {
                        int col = j * 8 + (lane & 3) * 2;
                        *(uint32_t*)(kh + base + col) = hw[j];
                    }
                }
                if (tt == 7) {
                    size_t base = ((size_t)(b * 64 + head * 8 + 7) * HW + p) * 32;
#pragma unroll
                    for (int j = 0; j < 4; j++) {
                        int col = j * 8 + (lane & 3) * 2;
                        *(uint32_t*)(kh + base + col) = hw[j];
                    }
                }
            }
        }
    }
}

// =================================================================================
// GEMM4: out = v @ w_proj^T + bias, fp32 out (unchanged proven path)
// =================================================================================
__global__ void __launch_bounds__(256, 2)
gemm_proj(const __nv_bfloat16* __restrict__ Ahi, const __nv_bfloat16* __restrict__ Alo,
          const __nv_bfloat16* __restrict__ Bhi, const __nv_bfloat16* __restrict__ Blo,
          const float* __restrict__ bias, float* __restrict__ C, int ldc)
{
    extern __shared__ char smg[];
    const uint32_t sb = smem_u32(smg);
    const int tid = threadIdx.x;
    const int lane = tid & 31;
    const int wid = tid >> 5;
    const int m0 = blockIdx.y * 128;
    const int n0 = blockIdx.x * 128;
    const int wm = (wid >> 2) * 64;
    const int wn = (wid & 3) * 32;

    float acc[4][4][4];
    gemm_mainloop(Ahi, Alo, Bhi, Blo, sb, m0, n0, tid, lane, wm, wn, acc);

#pragma unroll
    for (int j = 0; j < 4; j++) {
        int c = n0 + wn + j * 8 + (lane & 3) * 2;
        float b0 = bias[c], b1 = bias[c + 1];
#pragma unroll
        for (int i = 0; i < 4; i++) {
            int r = m0 + wm + i * 16 + (lane >> 2);
            *(float2*)(C + (size_t)r * ldc + c) =
                make_float2(acc[i][j][0] + b0, acc[i][j][1] + b1);
            *(float2*)(C + (size_t)(r + 8) * ldc + c) =
                make_float2(acc[i][j][2] + b0, acc[i][j][3] + b1);
        }
    }
}

// =================================================================================
// corr_proj v3 (fp16-single correlation path): 4 y-rows/block, 8 warps, 3 CTAs/SM.
// smem (67584 B):
//   q     @0      (8192 : 128 px x 64B)
//   k     @8192   (25600: 10 rows x 40 px x 64B, swizzled, zero halo)
//   w     @33792  (4096 : 32 e x 128B fp16)
//   corr  @37888 + w*2048 (per warp: 16 rows x 128B fp16)
//   sbuf  @54272 + w*1664 (per warp fp32 staging [16][26])
// =================================================================================
#define CPK_K  8192u
#define CPK_W  33792u
#define CPK_CS 37888u
#define CPK_SB 54272u
#define CPK_SMEM 67584

__global__ void __launch_bounds__(256, 3)
corr_proj(const __half* __restrict__ qh, const __half* __restrict__ kh,
          const __half* __restrict__ wch, const float* __restrict__ bc,
          __nv_bfloat16* __restrict__ vhi, __nv_bfloat16* __restrict__ vlo)
{
    extern __shared__ char sm[];
    const uint32_t sb = smem_u32(sm);
    const int tid  = threadIdx.x;
    const int lane = tid & 31;
    const int w    = tid >> 5;           // warp = segment 0..7
    const int img  = blockIdx.x >> 3;
    const int yq   = (blockIdx.x & 7) * 4;

    // zero k region (25600 B = 1600 uint4)
    for (int i = tid; i < 1600; i += 256)
        ((uint4*)(sm + CPK_K))[i] = make_uint4(0, 0, 0, 0);
    __syncthreads();

    // q fill: 128 px x 4 chunks = 512 cp16
    for (int i = tid; i < 512; i += 256) {
        int px = i >> 2, c = i & 3;
        const __half* src = qh + ((size_t)img * HW + yq * 32 + px) * 32 + c * 8;
        uint32_t dst = sb + px * 64 + ((c ^ ((px >> 1) & 3)) << 4);
        cp16(dst, src);
    }
    // k fill: 10 rows x 32 px x 4 chunks = 1280 cp16 (valid rows only)
    for (int i = tid; i < 1280; i += 256) {
        int row = i >> 7;
        int r2  = i & 127;
        int px  = r2 >> 2;
        int c   = r2 & 3;
        int y = yq - 3 + row;
        if (y >= 0 && y < 32) {
            int rlin = row * 40 + px + 3;
            uint32_t dst = sb + CPK_K + rlin * 64 + ((c ^ ((rlin >> 1) & 3)) << 4);
            cp16(dst, kh + ((size_t)img * HW + y * 32 + px) * 32 + c * 8);
        }
    }
    // w fill: 32 rows x 8 chunks = 256 cp16 (one per thread)
    {
        int r = tid >> 3, chk = tid & 7;
        uint32_t dst = sb + CPK_W + r * 128 + ((chk ^ (r & 7)) << 4);
        cp16(dst, wch + r * 64 + chk * 8);
    }
    CP_COMMIT();
    CP_WAIT0();
    __syncthreads();

    const int yloc = w >> 1;            // 0..3
    const int x0   = (w & 1) * 16;

    // A fragments (q, fp16, reused across all dy): 2 k16 chunks
    uint32_t Ah[2][4];
#pragma unroll
    for (int f = 0; f < 2; f++) {
        uint32_t r = w * 16 + (lane & 15);
        uint32_t c = f * 2 + (lane >> 4);
        uint32_t addr = sb + r * 64 + ((c ^ ((r >> 1) & 3)) << 4);
        LDSM4(Ah[f][0], Ah[f][1], Ah[f][2], Ah[f][3], addr);
    }

    float* sbuf = (float*)(sm + CPK_SB + w * 1664);   // [16][26], band-read stride 27
    const uint32_t cs = CPK_CS + w * 2048;
    const int lq = lane >> 2, lr = lane & 3;
    const int rr = lane >> 1;                          // band row 0..15
    const int odd = lane & 1;

#pragma unroll 1
    for (int dy = 0; dy < 7; dy++) {
        const int row = yloc + dy;                     // 0..9
        uint32_t Bh[3][4];
#pragma unroll
        for (int nt = 0; nt < 3; nt++) {
            uint32_t rlin = row * 40 + x0 + nt * 8 + (lane & 7);
            uint32_t c = lane >> 3;
            uint32_t addr = sb + CPK_K + rlin * 64 + ((c ^ ((rlin >> 1) & 3)) << 4);
            LDSM4(Bh[nt][0], Bh[nt][1], Bh[nt][2], Bh[nt][3], addr);
        }
        float acc[3][4];
#pragma unroll
        for (int nt = 0; nt < 3; nt++)
#pragma unroll
            for (int q = 0; q < 4; q++) acc[nt][q] = 0.f;

#pragma unroll
        for (int nt = 0; nt < 3; nt++) {
            MMA16816H(acc[nt], Ah[0][0], Ah[0][1], Ah[0][2], Ah[0][3], Bh[nt][0], Bh[nt][1]);
            MMA16816H(acc[nt], Ah[1][0], Ah[1][1], Ah[1][2], Ah[1][3], Bh[nt][2], Bh[nt][3]);
        }

        __syncwarp();
#pragma unroll
        for (int nt = 0; nt < 3; nt++) {
            *(float2*)&sbuf[lq * 26 + nt * 8 + lr * 2]       = make_float2(acc[nt][0], acc[nt][1]);
            *(float2*)&sbuf[(lq + 8) * 26 + nt * 8 + lr * 2] = make_float2(acc[nt][2], acc[nt][3]);
        }
        __syncwarp();

        // band extract row rr (cols rr..rr+6, stride-27 read) -> fp16 corr buf
        {
            uint32_t coff = rr * 128 + ((dy ^ (rr & 7)) << 4) + odd * 8;
            if (!odd) {
                uint32_t u0 = h2u(sbuf[27 * rr + 0], sbuf[27 * rr + 1]);
                uint32_t u1 = h2u(sbuf[27 * rr + 2], sbuf[27 * rr + 3]);
                *(uint2*)(sm + cs + coff) = make_uint2(u0, u1);
            } else {
                uint32_t u0 = h2u(sbuf[27 * rr + 4], sbuf[27 * rr + 5]);
                uint32_t u1 = h2u(sbuf[27 * rr + 6], 0.f);
                *(uint2*)(sm + cs + coff) = make_uint2(u0, u1);
            }
        }
        __syncwarp();
    }

    // zero tail chunk j' = 56..63
    {
        uint32_t coff = rr * 128 + ((7 ^ (rr & 7)) << 4) + odd * 8;
        *(uint2*)(sm + cs + coff) = make_uint2(0, 0);
    }
    __syncwarp();

    // ---------- Phase 2: projection m16 x n32 x k64, fp16 single ----------
    float pacc[4][4];
#pragma unroll
    for (int n = 0; n < 4; n++)
#pragma unroll
        for (int q = 0; q < 4; q++) pacc[n][q] = 0.f;

#pragma unroll
    for (int k = 0; k < 4; k++) {
        uint32_t bh[4][2];
#pragma unroll
        for (int n = 0; n < 4; n++) {
            uint32_t wr = n * 8 + lq;
            uint32_t o0 = wr * 128 + (((2 * k)     ^ (wr & 7)) << 4) + lr * 4;
            uint32_t o1 = wr * 128 + (((2 * k + 1) ^ (wr & 7)) << 4) + lr * 4;
            bh[n][0] = *(const uint32_t*)(sm + CPK_W + o0);
            bh[n][1] = *(const uint32_t*)(sm + CPK_W + o1);
        }
        uint32_t r0 = lq, r1 = lq + 8;
        uint32_t a00 = r0 * 128 + (((2 * k)     ^ (r0 & 7)) << 4) + lr * 4;
        uint32_t a10 = r1 * 128 + (((2 * k)     ^ (r1 & 7)) << 4) + lr * 4;
        uint32_t a01 = r0 * 128 + (((2 * k + 1) ^ (r0 & 7)) << 4) + lr * 4;
        uint32_t a11 = r1 * 128 + (((2 * k + 1) ^ (r1 & 7)) << 4) + lr * 4;
        uint32_t Pa[4];
        Pa[0] = *(const uint32_t*)(sm + cs + a00);
        Pa[1] = *(const uint32_t*)(sm + cs + a10);
        Pa[2] = *(const uint32_t*)(sm + cs + a01);
        Pa[3] = *(const uint32_t*)(sm + cs + a11);
#pragma unroll
        for (int n = 0; n < 4; n++)
            MMA16816H(pacc[n], Pa[0], Pa[1], Pa[2], Pa[3], bh[n][0], bh[n][1]);
    }

    // epilogue: v + b_corr, split to bf16 hi/lo (feeds 3-term out-GEMM)
    const int b    = img >> 6;
    const int head = (img >> 3) & 7;
    const int t    = img & 7;
    const int y    = yq + yloc;
    const int p0   = y * 32 + x0 + lq;
#pragma unroll
    for (int n = 0; n < 4; n++) {
        int col = n * 8 + lr * 2;
        float b0 = bc[col], b1 = bc[col + 1];
        size_t row0 = (size_t)b * N_ + t * HW + p0;
        size_t g0 = row0 * C_ + head * 32 + col;
        size_t g1 = (row0 + 8) * C_ + head * 32 + col;
        uint32_t h0, l0, h1, l1;
        split_bf16x2(pacc[n][0] + b0, pacc[n][1] + b1, h0, l0);
        split_bf16x2(pacc[n][2] + b0, pacc[n][3] + b1, h1, l1);
        *(uint32_t*)(vhi + g0) = h0;
        *(uint32_t*)(vlo + g0) = l0;
        *(uint32_t*)(vhi + g1) = h1;
        *(uint32_t*)(vlo + g1) = l1;
    }
}

// =================================================================================
extern "C" void kernel_launch(void* const* d_in, const int* in_sizes, int n_in,
                              void* d_out, int out_size)
{
    const float* x      = (const float*)d_in[0];
    const float* w_qk   = (const float*)d_in[1];
    const float* w_corr = (const float*)d_in[2];
    const float* b_corr = (const float*)d_in[3];
    const float* w_proj = (const float*)d_in[4];
    const float* b_proj = (const float*)d_in[5];
    float* out = (float*)d_out;

    __half *qhp, *khp, *wcp;
    __nv_bfloat16 *xhi, *xlo, *vhi, *vlo, *wqh, *wql, *wph, *wpl;
    cudaGetSymbolAddress((void**)&qhp, g_qh);
    cudaGetSymbolAddress((void**)&khp, g_kh);
    cudaGetSymbolAddress((void**)&wcp, g_wcT);
    cudaGetSymbolAddress((void**)&xhi, g_xhi);
    cudaGetSymbolAddress((void**)&xlo, g_xlo);
    cudaGetSymbolAddress((void**)&vhi, g_vhi);
    cudaGetSymbolAddress((void**)&vlo, g_vlo);
    cudaGetSymbolAddress((void**)&wqh, g_wqk_hi);
    cudaGetSymbolAddress((void**)&wql, g_wqk_lo);
    cudaGetSymbolAddress((void**)&wph, g_wpj_hi);
    cudaGetSymbolAddress((void**)&wpl, g_wpj_lo);

    cudaFuncSetAttribute(gemm_qk,   cudaFuncAttributeMaxDynamicSharedMemorySize, GM_SMEM);
    cudaFuncSetAttribute(gemm_proj, cudaFuncAttributeMaxDynamicSharedMemorySize, GM_SMEM);
    cudaFuncSetAttribute(corr_proj, cudaFuncAttributeMaxDynamicSharedMemorySize, CPK_SMEM);

    // 0) hi/lo splits + w_corr prep
    conv_split<<<(M_TOT * C_ / 4 + 255) / 256, 256>>>((const float4*)x, (uint2*)xhi, (uint2*)xlo, M_TOT * C_ / 4);
    conv_split<<<(512 * 256 / 4 + 255) / 256, 256>>>((const float4*)w_qk, (uint2*)wqh, (uint2*)wql, 512 * 256 / 4);
    conv_split<<<(256 * 256 / 4 + 255) / 256, 256>>>((const float4*)w_proj, (uint2*)wph, (uint2*)wpl, 256 * 256 / 4);
    prep_w<<<8, 256>>>(w_corr, wcp);

    // 1) qk GEMM fused with normalize + temporal shift -> q/k fp16
    gemm_qk<<<dim3(4, 512), 256, GM_SMEM>>>(xhi, xlo, wqh, wql, qhp, khp);

    // 2) fused banded tensor-core correlation + projection (3 CTAs/SM) -> v hi/lo
    corr_proj<<<BHT * 8, 256, CPK_SMEM>>>(qhp, khp, wcp, b_corr, vhi, vlo);

    // 3) out = v @ w_proj^T + b_proj
    gemm_proj<<<dim3(2, 512), 256, GM_SMEM>>>(vhi, vlo, wph, wpl, b_proj, out, 256);
}

// round 14
// speedup vs baseline: 1.4986x; 1.2452x over previous
#include <cuda_runtime.h>
#include <cuda_bf16.h>
#include <cuda_fp16.h>
#include <math.h>
#include <stdint.h>

#define B_    8
#define NH    8
#define T_    8
#define HD    32
#define C_    256
#define N_    8192
#define HW    1024
#define BHT   512            // B*NH*T
#define M_TOT 65536          // B*N

// ---------------- scratch (static device globals; no allocation) ----------------
__device__ __half g_qh[(size_t)BHT * HW * 32];         // q fp16 [img][px][ch]
__device__ __half g_kh[(size_t)BHT * HW * 32];         // k fp16 (shifted) [img][px][ch]
__device__ __half g_xhi[(size_t)M_TOT * C_];           // x fp16 hi
__device__ __half g_xlo[(size_t)M_TOT * C_];           // x fp16 lo (residual)
__device__ __half g_vhi[(size_t)M_TOT * C_];           // v fp16 hi
__device__ __half g_vlo[(size_t)M_TOT * C_];           // v fp16 lo
__device__ __half g_wqk[512 * 256];                    // w_qk fp16 single
__device__ __half g_wpj[256 * 256];                    // w_proj fp16 single
__device__ __half g_wcT[32 * 64];                      // w_corr fp16 [e][j'=dy*8+dx]

// ======================= asm helpers ==================
__device__ __forceinline__ uint32_t smem_u32(const void* p) {
    uint32_t a;
    asm("{ .reg .u64 t; cvta.to.shared.u64 t, %1; cvt.u32.u64 %0, t; }" : "=r"(a) : "l"(p));
    return a;
}
__device__ __forceinline__ void cp16(uint32_t saddr, const void* g) {
    asm volatile("cp.async.cg.shared.global [%0], [%1], 16;" :: "r"(saddr), "l"(g));
}
#define CP_COMMIT() asm volatile("cp.async.commit_group;" ::: "memory")
#define CP_WAIT1()  asm volatile("cp.async.wait_group 1;" ::: "memory")
#define CP_WAIT0()  asm volatile("cp.async.wait_group 0;" ::: "memory")

#define LDSM4(r0, r1, r2, r3, addr) \
    asm volatile("ldmatrix.sync.aligned.m8n8.x4.shared.b16 {%0,%1,%2,%3}, [%4];" \
                 : "=r"(r0), "=r"(r1), "=r"(r2), "=r"(r3) : "r"(addr))
// fp16 mma
#define MMA16816H(c, a0, a1, a2, a3, b0, b1) \
    asm volatile("mma.sync.aligned.m16n8k16.row.col.f32.f16.f16.f32 " \
                 "{%0,%1,%2,%3},{%4,%5,%6,%7},{%8,%9},{%0,%1,%2,%3};" \
                 : "+f"((c)[0]), "+f"((c)[1]), "+f"((c)[2]), "+f"((c)[3]) \
                 : "r"(a0), "r"(a1), "r"(a2), "r"(a3), "r"(b0), "r"(b1))

__device__ __forceinline__ uint32_t h2u(float a, float b) {
    __half2 h = __floats2half2_rn(a, b);
    return *(uint32_t*)&h;
}
__device__ __forceinline__ void split_h16x2(float a, float b, uint32_t& hi, uint32_t& lo) {
    __half2 h = __floats2half2_rn(a, b);
    float r0 = a - __half2float(__low2half(h));
    float r1 = b - __half2float(__high2half(h));
    __half2 l = __floats2half2_rn(r0, r1);
    hi = *(uint32_t*)&h;
    lo = *(uint32_t*)&l;
}

// =================================================================================
// fp32 -> fp16 (hi, lo-residual) split, vectorized
__global__ void __launch_bounds__(256)
conv_split(const float4* __restrict__ in, uint2* __restrict__ hi,
           uint2* __restrict__ lo, int n4)
{
    int i = blockIdx.x * 256 + threadIdx.x;
    if (i >= n4) return;
    float4 f = in[i];
    uint32_t h0, l0, h1, l1;
    split_h16x2(f.x, f.y, h0, l0);
    split_h16x2(f.z, f.w, h1, l1);
    hi[i] = make_uint2(h0, h1);
    lo[i] = make_uint2(l0, l1);
}

// fp32 -> fp16 single
__global__ void __launch_bounds__(256)
conv_half(const float4* __restrict__ in, uint2* __restrict__ out, int n4)
{
    int i = blockIdx.x * 256 + threadIdx.x;
    if (i >= n4) return;
    float4 f = in[i];
    out[i] = make_uint2(h2u(f.x, f.y), h2u(f.z, f.w));
}

// w_corr [32 e][49 j] -> padded fp16 [32 e][64 j'] with j' = dy*8+dx
__global__ void __launch_bounds__(256)
prep_w(const float* __restrict__ wc, __half* __restrict__ wh)
{
    int i = blockIdx.x * 256 + threadIdx.x;
    if (i >= 32 * 64) return;
    int e = i >> 6, jp = i & 63;
    int dy = jp >> 3, dx = jp & 7;
    float v = (dy < 7 && dx < 7) ? wc[e * 49 + dy * 7 + dx] : 0.f;
    wh[i] = __float2half(v);
}

// =================================================================================
// 2-term fp16 GEMM machinery: 128x128 block, BK=32, K=256, 3-stage cp.async.
// C = (Ahi + Alo) * Bh ; stage = Ahi(8K) | Alo(8K) | Bh(8K) = 24KB.
// =================================================================================
#define KGEMM 256
#define NTILES 8
#define GM_STAGE 24576
#define GM_SMEM  (3 * GM_STAGE)   // 73728

__device__ __forceinline__ void stage_load(
    uint32_t sbase, const __half* __restrict__ Ahi, const __half* __restrict__ Alo,
    const __half* __restrict__ Bh, int m0, int n0, int kt, int tid)
{
    int row = tid >> 1;
    int cb  = (tid & 1) * 2;
#pragma unroll
    for (int j = 0; j < 2; j++) {
        int c16 = cb + j;
        uint32_t soff = (uint32_t)(row * 64 + ((c16 ^ ((row >> 1) & 3)) << 4));
        size_t ga = (size_t)row * KGEMM + kt * 32 + c16 * 8;
        cp16(sbase +     0 + soff, Ahi + (size_t)m0 * KGEMM + ga);
        cp16(sbase +  8192 + soff, Alo + (size_t)m0 * KGEMM + ga);
        cp16(sbase + 16384 + soff, Bh + (size_t)n0 * KGEMM + ga);
    }
}

__device__ __forceinline__ void mma_ks_body(
    uint32_t aBase, uint32_t bBase, int ks, int lane, int wm, int wn,
    float acc[4][4][4])
{
    const uint32_t l2 = lane & 15;
    uint32_t aaddr[4], baddr[2];
    {
        uint32_t achk = (uint32_t)(ks * 2) + (lane >> 4);
#pragma unroll
        for (int i = 0; i < 4; i++) {
            uint32_t r = wm + l2 + i * 16;
            aaddr[i] = aBase + r * 64 + ((achk ^ ((r >> 1) & 3)) << 4);
        }
        uint32_t bchk = (uint32_t)(ks * 2) + ((l2 >> 3) & 1);
#pragma unroll
        for (int jj = 0; jj < 2; jj++) {
            uint32_t jt = jj * 2 + (lane >> 4);       // tile index for this lane's addr
            uint32_t r = wn + (l2 & 7) + jt * 8;
            baddr[jj] = bBase + r * 64 + ((bchk ^ ((r >> 1) & 3)) << 4);
        }
    }
    uint32_t a[4][4], al[4][4], b[8];
#pragma unroll
    for (int i = 0; i < 4; i++) LDSM4(a[i][0], a[i][1], a[i][2], a[i][3], aaddr[i]);
    LDSM4(b[0], b[1], b[2], b[3], baddr[0]);   // n-tiles 0,1
    LDSM4(b[4], b[5], b[6], b[7], baddr[1]);   // n-tiles 2,3
#pragma unroll
    for (int i = 0; i < 4; i++) LDSM4(al[i][0], al[i][1], al[i][2], al[i][3], aaddr[i] + 8192);
#pragma unroll
    for (int i = 0; i < 4; i++)
#pragma unroll
        for (int j = 0; j < 4; j++)
            MMA16816H(acc[i][j], a[i][0], a[i][1], a[i][2], a[i][3], b[2 * j], b[2 * j + 1]);
#pragma unroll
    for (int i = 0; i < 4; i++)
#pragma unroll
        for (int j = 0; j < 4; j++)
            MMA16816H(acc[i][j], al[i][0], al[i][1], al[i][2], al[i][3], b[2 * j], b[2 * j + 1]);
}

__device__ __forceinline__ void gemm_mainloop(
    const __half* __restrict__ Ahi, const __half* __restrict__ Alo,
    const __half* __restrict__ Bh,
    uint32_t sb, int m0, int n0, int tid, int lane, int wm, int wn,
    float acc[4][4][4])
{
#pragma unroll
    for (int i = 0; i < 4; i++)
#pragma unroll
        for (int j = 0; j < 4; j++)
#pragma unroll
            for (int q = 0; q < 4; q++) acc[i][j][q] = 0.f;

    stage_load(sb,            Ahi, Alo, Bh, m0, n0, 0, tid);
    CP_COMMIT();
    stage_load(sb + GM_STAGE, Ahi, Alo, Bh, m0, n0, 1, tid);
    CP_COMMIT();

    int stage = 0;
    int lstage = 2;
    for (int kt = 0; kt < NTILES; kt++) {
        CP_WAIT1();
        __syncthreads();
        if (kt + 2 < NTILES)
            stage_load(sb + lstage * GM_STAGE, Ahi, Alo, Bh, m0, n0, kt + 2, tid);
        CP_COMMIT();
        lstage = stage;

        const uint32_t sa = sb + stage * GM_STAGE;
        stage = (stage == 2) ? 0 : stage + 1;

#pragma unroll
        for (int ks = 0; ks < 2; ks++)
            mma_ks_body(sa, sa + 16384, ks, lane, wm, wn, acc);
    }
}

// =================================================================================
// GEMM1 fused: qk GEMM (fp16 2-term) + L2-normalize + temporal shift ->
// q/k fp16 single [img][px][ch].
// =================================================================================
__global__ void __launch_bounds__(256, 2)
gemm_qk(const __half* __restrict__ Ahi, const __half* __restrict__ Alo,
        const __half* __restrict__ Bh,
        __half* __restrict__ qh, __half* __restrict__ kh)
{
    const bool is_k = (blockIdx.x >= 2);
    const int tt_blk = (blockIdx.y >> 3) & 7;
    if (is_k && tt_blk == 0) return;        // dead k tile (shifted away)

    extern __shared__ char smg[];
    const uint32_t sb = smem_u32(smg);
    const int tid = threadIdx.x;
    const int lane = tid & 31;
    const int wid = tid >> 5;
    const int m0 = blockIdx.y * 128;
    const int n0 = blockIdx.x * 128;
    const int wm = (wid >> 2) * 64;
    const int wn = (wid & 3) * 32;

    float acc[4][4][4];
    gemm_mainloop(Ahi, Alo, Bh, sb, m0, n0, tid, lane, wm, wn, acc);

    const int head = (((n0 & 255) + wn) >> 5);

#pragma unroll
    for (int i = 0; i < 4; i++) {
#pragma unroll
        for (int h = 0; h < 2; h++) {
            float v0[4], v1[4];
            float ss = 0.f;
#pragma unroll
            for (int j = 0; j < 4; j++) {
                v0[j] = acc[i][j][2 * h];
                v1[j] = acc[i][j][2 * h + 1];
                ss += v0[j] * v0[j] + v1[j] * v1[j];
            }
            ss += __shfl_xor_sync(0xffffffffu, ss, 1);
            ss += __shfl_xor_sync(0xffffffffu, ss, 2);
            float inv = 1.0f / fmaxf(sqrtf(ss), 1e-12f);

            int r = m0 + wm + i * 16 + (lane >> 2) + h * 8;
            int b  = r >> 13;
            int tt = (r >> 10) & 7;
            int p  = r & 1023;

            uint32_t hw[4];
#pragma unroll
            for (int j = 0; j < 4; j++) hw[j] = h2u(v0[j] * inv, v1[j] * inv);

            if (!is_k) {
                size_t base = ((size_t)(b * 64 + head * 8 + tt) * HW + p) * 32;
#pragma unroll
                for (int j = 0; j < 4; j++) {
                    int col = j * 8 + (lane & 3) * 2;
                    *(uint32_t*)(qh + base + col) = hw[j];
                }
            } else {
                if (tt >= 1) {
                    size_t base = ((size_t)(b * 64 + head * 8 + (tt - 1)) * HW + p) * 32;
#pragma unroll
                    for (int j = 0; j < 4; j++) {
                        int col = j * 8 + (lane & 3) * 2;
                        *(uint32_t*)(kh + base + col) = hw[j];
                    }
                }
                if (tt == 7) {
                    size_t base = ((size_t)(b * 64 + head * 8 + 7) * HW + p) * 32;
#pragma unroll
                    for (int j = 0; j < 4; j++) {
                        int col = j * 8 + (lane & 3) * 2;
                        *(uint32_t*)(kh + base + col) = hw[j];
                    }
                }
            }
        }
    }
}

// =================================================================================
// GEMM4: out = v @ w_proj^T + bias (fp16 2-term), fp32 out
// =================================================================================
__global__ void __launch_bounds__(256, 2)
gemm_proj(const __half* __restrict__ Ahi, const __half* __restrict__ Alo,
          const __half* __restrict__ Bh,
          const float* __restrict__ bias, float* __restrict__ C, int ldc)
{
    extern __shared__ char smg[];
    const uint32_t sb = smem_u32(smg);
    const int tid = threadIdx.x;
    const int lane = tid & 31;
    const int wid = tid >> 5;
    const int m0 = blockIdx.y * 128;
    const int n0 = blockIdx.x * 128;
    const int wm = (wid >> 2) * 64;
    const int wn = (wid & 3) * 32;

    float acc[4][4][4];
    gemm_mainloop(Ahi, Alo, Bh, sb, m0, n0, tid, lane, wm, wn, acc);

#pragma unroll
    for (int j = 0; j < 4; j++) {
        int c = n0 + wn + j * 8 + (lane & 3) * 2;
        float b0 = bias[c], b1 = bias[c + 1];
#pragma unroll
        for (int i = 0; i < 4; i++) {
            int r = m0 + wm + i * 16 + (lane >> 2);
            *(float2*)(C + (size_t)r * ldc + c) =
                make_float2(acc[i][j][0] + b0, acc[i][j][1] + b1);
            *(float2*)(C + (size_t)(r + 8) * ldc + c) =
                make_float2(acc[i][j][2] + b0, acc[i][j][3] + b1);
        }
    }
}

// =================================================================================
// corr_proj (fp16-single correlation path, proven): 4 y-rows/block, 8 warps,
// 3 CTAs/SM. Epilogue now emits v as fp16 hi/lo (feeds 2-term out-GEMM).
// =================================================================================
#define CPK_K  8192u
#define CPK_W  33792u
#define CPK_CS 37888u
#define CPK_SB 54272u
#define CPK_SMEM 67584

__global__ void __launch_bounds__(256, 3)
corr_proj(const __half* __restrict__ qh, const __half* __restrict__ kh,
          const __half* __restrict__ wch, const float* __restrict__ bc,
          __half* __restrict__ vhi, __half* __restrict__ vlo)
{
    extern __shared__ char sm[];
    const uint32_t sb = smem_u32(sm);
    const int tid  = threadIdx.x;
    const int lane = tid & 31;
    const int w    = tid >> 5;           // warp = segment 0..7
    const int img  = blockIdx.x >> 3;
    const int yq   = (blockIdx.x & 7) * 4;

    for (int i = tid; i < 1600; i += 256)
        ((uint4*)(sm + CPK_K))[i] = make_uint4(0, 0, 0, 0);
    __syncthreads();

    for (int i = tid; i < 512; i += 256) {
        int px = i >> 2, c = i & 3;
        const __half* src = qh + ((size_t)img * HW + yq * 32 + px) * 32 + c * 8;
        uint32_t dst = sb + px * 64 + ((c ^ ((px >> 1) & 3)) << 4);
        cp16(dst, src);
    }
    for (int i = tid; i < 1280; i += 256) {
        int row = i >> 7;
        int r2  = i & 127;
        int px  = r2 >> 2;
        int c   = r2 & 3;
        int y = yq - 3 + row;
        if (y >= 0 && y < 32) {
            int rlin = row * 40 + px + 3;
            uint32_t dst = sb + CPK_K + rlin * 64 + ((c ^ ((rlin >> 1) & 3)) << 4);
            cp16(dst, kh + ((size_t)img * HW + y * 32 + px) * 32 + c * 8);
        }
    }
    {
        int r = tid >> 3, chk = tid & 7;
        uint32_t dst = sb + CPK_W + r * 128 + ((chk ^ (r & 7)) << 4);
        cp16(dst, wch + r * 64 + chk * 8);
    }
    CP_COMMIT();
    CP_WAIT0();
    __syncthreads();

    const int yloc = w >> 1;
    const int x0   = (w & 1) * 16;

    uint32_t Ah[2][4];
#pragma unroll
    for (int f = 0; f < 2; f++) {
        uint32_t r = w * 16 + (lane & 15);
        uint32_t c = f * 2 + (lane >> 4);
        uint32_t addr = sb + r * 64 + ((c ^ ((r >> 1) & 3)) << 4);
        LDSM4(Ah[f][0], Ah[f][1], Ah[f][2], Ah[f][3], addr);
    }

    float* sbuf = (float*)(sm + CPK_SB + w * 1664);
    const uint32_t cs = CPK_CS + w * 2048;
    const int lq = lane >> 2, lr = lane & 3;
    const int rr = lane >> 1;
    const int odd = lane & 1;

#pragma unroll 1
    for (int dy = 0; dy < 7; dy++) {
        const int row = yloc + dy;
        uint32_t Bt[3][4];
#pragma unroll
        for (int nt = 0; nt < 3; nt++) {
            uint32_t rlin = row * 40 + x0 + nt * 8 + (lane & 7);
            uint32_t c = lane >> 3;
            uint32_t addr = sb + CPK_K + rlin * 64 + ((c ^ ((rlin >> 1) & 3)) << 4);
            LDSM4(Bt[nt][0], Bt[nt][1], Bt[nt][2], Bt[nt][3], addr);
        }
        float acc[3][4];
#pragma unroll
        for (int nt = 0; nt < 3; nt++)
#pragma unroll
            for (int q = 0; q < 4; q++) acc[nt][q] = 0.f;

#pragma unroll
        for (int nt = 0; nt < 3; nt++) {
            MMA16816H(acc[nt], Ah[0][0], Ah[0][1], Ah[0][2], Ah[0][3], Bt[nt][0], Bt[nt][1]);
            MMA16816H(acc[nt], Ah[1][0], Ah[1][1], Ah[1][2], Ah[1][3], Bt[nt][2], Bt[nt][3]);
        }

        __syncwarp();
#pragma unroll
        for (int nt = 0; nt < 3; nt++) {
            *(float2*)&sbuf[lq * 26 + nt * 8 + lr * 2]       = make_float2(acc[nt][0], acc[nt][1]);
            *(float2*)&sbuf[(lq + 8) * 26 + nt * 8 + lr * 2] = make_float2(acc[nt][2], acc[nt][3]);
        }
        __syncwarp();

        {
            uint32_t coff = rr * 128 + ((dy ^ (rr & 7)) << 4) + odd * 8;
            if (!odd) {
                uint32_t u0 = h2u(sbuf[27 * rr + 0], sbuf[27 * rr + 1]);
                uint32_t u1 = h2u(sbuf[27 * rr + 2], sbuf[27 * rr + 3]);
                *(uint2*)(sm + cs + coff) = make_uint2(u0, u1);
            } else {
                uint32_t u0 = h2u(sbuf[27 * rr + 4], sbuf[27 * rr + 5]);
                uint32_t u1 = h2u(sbuf[27 * rr + 6], 0.f);
                *(uint2*)(sm + cs + coff) = make_uint2(u0, u1);
            }
        }
        __syncwarp();
    }

    {
        uint32_t coff = rr * 128 + ((7 ^ (rr & 7)) << 4) + odd * 8;
        *(uint2*)(sm + cs + coff) = make_uint2(0, 0);
    }
    __syncwarp();

    // Phase 2: projection m16 x n32 x k64, fp16 single
    float pacc[4][4];
#pragma unroll
    for (int n = 0; n < 4; n++)
#pragma unroll
        for (int q = 0; q < 4; q++) pacc[n][q] = 0.f;

#pragma unroll
    for (int k = 0; k < 4; k++) {
        uint32_t bh[4][2];
#pragma unroll
        for (int n = 0; n < 4; n++) {
            uint32_t wr = n * 8 + lq;
            uint32_t o0 = wr * 128 + (((2 * k)     ^ (wr & 7)) << 4) + lr * 4;
            uint32_t o1 = wr * 128 + (((2 * k + 1) ^ (wr & 7)) << 4) + lr * 4;
            bh[n][0] = *(const uint32_t*)(sm + CPK_W + o0);
            bh[n][1] = *(const uint32_t*)(sm + CPK_W + o1);
        }
        uint32_t r0 = lq, r1 = lq + 8;
        uint32_t a00 = r0 * 128 + (((2 * k)     ^ (r0 & 7)) << 4) + lr * 4;
        uint32_t a10 = r1 * 128 + (((2 * k)     ^ (r1 & 7)) << 4) + lr * 4;
        uint32_t a01 = r0 * 128 + (((2 * k + 1) ^ (r0 & 7)) << 4) + lr * 4;
        uint32_t a11 = r1 * 128 + (((2 * k + 1) ^ (r1 & 7)) << 4) + lr * 4;
        uint32_t Pa[4];
        Pa[0] = *(const uint32_t*)(sm + cs + a00);
        Pa[1] = *(const uint32_t*)(sm + cs + a10);
        Pa[2] = *(const uint32_t*)(sm + cs + a01);
        Pa[3] = *(const uint32_t*)(sm + cs + a11);
#pragma unroll
        for (int n = 0; n < 4; n++)
            MMA16816H(pacc[n], Pa[0], Pa[1], Pa[2], Pa[3], bh[n][0], bh[n][1]);
    }

    // epilogue: v + b_corr, split to fp16 hi/lo (feeds 2-term out-GEMM)
    const int b    = img >> 6;
    const int head = (img >> 3) & 7;
    const int t    = img & 7;
    const int y    = yq + yloc;
    const int p0   = y * 32 + x0 + lq;
#pragma unroll
    for (int n = 0; n < 4; n++) {
        int col = n * 8 + lr * 2;
        float b0 = bc[col], b1 = bc[col + 1];
        size_t row0 = (size_t)b * N_ + t * HW + p0;
        size_t g0 = row0 * C_ + head * 32 + col;
        size_t g1 = (row0 + 8) * C_ + head * 32 + col;
        uint32_t h0, l0, h1, l1;
        split_h16x2(pacc[n][0] + b0, pacc[n][1] + b1, h0, l0);
        split_h16x2(pacc[n][2] + b0, pacc[n][3] + b1, h1, l1);
        *(uint32_t*)(vhi + g0) = h0;
        *(uint32_t*)(vlo + g0) = l0;
        *(uint32_t*)(vhi + g1) = h1;
        *(uint32_t*)(vlo + g1) = l1;
    }
}

// =================================================================================
extern "C" void kernel_launch(void* const* d_in, const int* in_sizes, int n_in,
                              void* d_out, int out_size)
{
    const float* x      = (const float*)d_in[0];
    const float* w_qk   = (const float*)d_in[1];
    const float* w_corr = (const float*)d_in[2];
    const float* b_corr = (const float*)d_in[3];
    const float* w_proj = (const float*)d_in[4];
    const float* b_proj = (const float*)d_in[5];
    float* out = (float*)d_out;

    __half *qhp, *khp, *wcp, *xhi, *xlo, *vhi, *vlo, *wqk, *wpj;
    cudaGetSymbolAddress((void**)&qhp, g_qh);
    cudaGetSymbolAddress((void**)&khp, g_kh);
    cudaGetSymbolAddress((void**)&wcp, g_wcT);
    cudaGetSymbolAddress((void**)&xhi, g_xhi);
    cudaGetSymbolAddress((void**)&xlo, g_xlo);
    cudaGetSymbolAddress((void**)&vhi, g_vhi);
    cudaGetSymbolAddress((void**)&vlo, g_vlo);
    cudaGetSymbolAddress((void**)&wqk, g_wqk);
    cudaGetSymbolAddress((void**)&wpj, g_wpj);

    cudaFuncSetAttribute(gemm_qk,   cudaFuncAttributeMaxDynamicSharedMemorySize, GM_SMEM);
    cudaFuncSetAttribute(gemm_proj, cudaFuncAttributeMaxDynamicSharedMemorySize, GM_SMEM);
    cudaFuncSetAttribute(corr_proj, cudaFuncAttributeMaxDynamicSharedMemorySize, CPK_SMEM);

    // 0) conversions
    conv_split<<<(M_TOT * C_ / 4 + 255) / 256, 256>>>((const float4*)x, (uint2*)xhi, (uint2*)xlo, M_TOT * C_ / 4);
    conv_half<<<(512 * 256 / 4 + 255) / 256, 256>>>((const float4*)w_qk, (uint2*)wqk, 512 * 256 / 4);
    conv_half<<<(256 * 256 / 4 + 255) / 256, 256>>>((const float4*)w_proj, (uint2*)wpj, 256 * 256 / 4);
    prep_w<<<8, 256>>>(w_corr, wcp);

    // 1) qk GEMM (fp16 2-term) + normalize + shift -> q/k fp16
    gemm_qk<<<dim3(4, 512), 256, GM_SMEM>>>(xhi, xlo, wqk, qhp, khp);

    // 2) fused banded tensor-core correlation + projection (3 CTAs/SM) -> v fp16 hi/lo
    corr_proj<<<BHT * 8, 256, CPK_SMEM>>>(qhp, khp, wcp, b_corr, vhi, vlo);

    // 3) out = v @ w_proj^T + b_proj (fp16 2-term)
    gemm_proj<<<dim3(2, 512), 256, GM_SMEM>>>(vhi, vlo, wpj, b_proj, out, 256);
}

// round 15
// speedup vs baseline: 2.0664x; 1.3788x over previous
#include <cuda_runtime.h>
#include <cuda_fp16.h>
#include <math.h>
#include <stdint.h>

#define B_    8
#define NH    8
#define T_    8
#define HD    32
#define C_    256
#define N_    8192
#define HW    1024
#define BHT   512            // B*NH*T
#define M_TOT 65536          // B*N

// ---------------- scratch (static device globals; no allocation) ----------------
__device__ __half g_qh[(size_t)BHT * HW * 32];         // q fp16 [img][px][ch]
__device__ __half g_kh[(size_t)BHT * HW * 32];         // k fp16 (shifted) [img][px][ch]
__device__ __half g_x16[(size_t)M_TOT * C_];           // x fp16
__device__ __half g_v16[(size_t)M_TOT * C_];           // v fp16
__device__ __half g_wqk[512 * 256];                    // w_qk fp16
__device__ __half g_wpj[256 * 256];                    // w_proj fp16
__device__ __half g_wcT[32 * 64];                      // w_corr fp16 [e][j'=dy*8+dx]

// ======================= asm helpers ==================
__device__ __forceinline__ uint32_t smem_u32(const void* p) {
    uint32_t a;
    asm("{ .reg .u64 t; cvta.to.shared.u64 t, %1; cvt.u32.u64 %0, t; }" : "=r"(a) : "l"(p));
    return a;
}
__device__ __forceinline__ void cp16(uint32_t saddr, const void* g) {
    asm volatile("cp.async.cg.shared.global [%0], [%1], 16;" :: "r"(saddr), "l"(g));
}
#define CP_COMMIT() asm volatile("cp.async.commit_group;" ::: "memory")
#define CP_WAIT1()  asm volatile("cp.async.wait_group 1;" ::: "memory")
#define CP_WAIT0()  asm volatile("cp.async.wait_group 0;" ::: "memory")

#define LDSM4(r0, r1, r2, r3, addr) \
    asm volatile("ldmatrix.sync.aligned.m8n8.x4.shared.b16 {%0,%1,%2,%3}, [%4];" \
                 : "=r"(r0), "=r"(r1), "=r"(r2), "=r"(r3) : "r"(addr))
#define MMA16816H(c, a0, a1, a2, a3, b0, b1) \
    asm volatile("mma.sync.aligned.m16n8k16.row.col.f32.f16.f16.f32 " \
                 "{%0,%1,%2,%3},{%4,%5,%6,%7},{%8,%9},{%0,%1,%2,%3};" \
                 : "+f"((c)[0]), "+f"((c)[1]), "+f"((c)[2]), "+f"((c)[3]) \
                 : "r"(a0), "r"(a1), "r"(a2), "r"(a3), "r"(b0), "r"(b1))

__device__ __forceinline__ uint32_t h2u(float a, float b) {
    __half2 h = __floats2half2_rn(a, b);
    return *(uint32_t*)&h;
}

// =================================================================================
// fp32 -> fp16 single, vectorized
__global__ void __launch_bounds__(256)
conv_half(const float4* __restrict__ in, uint2* __restrict__ out, int n4)
{
    int i = blockIdx.x * 256 + threadIdx.x;
    if (i >= n4) return;
    float4 f = in[i];
    out[i] = make_uint2(h2u(f.x, f.y), h2u(f.z, f.w));
}

// w_corr [32 e][49 j] -> padded fp16 [32 e][64 j'] with j' = dy*8+dx
__global__ void __launch_bounds__(256)
prep_w(const float* __restrict__ wc, __half* __restrict__ wh)
{
    int i = blockIdx.x * 256 + threadIdx.x;
    if (i >= 32 * 64) return;
    int e = i >> 6, jp = i & 63;
    int dy = jp >> 3, dx = jp & 7;
    float v = (dy < 7 && dx < 7) ? wc[e * 49 + dy * 7 + dx] : 0.f;
    wh[i] = __float2half(v);
}

// =================================================================================
// 1-term fp16 GEMM machinery: 128x128 block, BK=32, K=256, 3-stage cp.async.
// C = A * B ; stage = A(8K) | B(8K) = 16KB.
// =================================================================================
#define KGEMM 256
#define NTILES 8
#define GM_STAGE 16384
#define GM_SMEM  (3 * GM_STAGE)   // 49152

__device__ __forceinline__ void stage_load(
    uint32_t sbase, const __half* __restrict__ A, const __half* __restrict__ Bh,
    int m0, int n0, int kt, int tid)
{
    int row = tid >> 1;
    int cb  = (tid & 1) * 2;
#pragma unroll
    for (int j = 0; j < 2; j++) {
        int c16 = cb + j;
        uint32_t soff = (uint32_t)(row * 64 + ((c16 ^ ((row >> 1) & 3)) << 4));
        size_t ga = (size_t)row * KGEMM + kt * 32 + c16 * 8;
        cp16(sbase +    0 + soff, A  + (size_t)m0 * KGEMM + ga);
        cp16(sbase + 8192 + soff, Bh + (size_t)n0 * KGEMM + ga);
    }
}

__device__ __forceinline__ void mma_ks_body(
    uint32_t aBase, uint32_t bBase, int ks, int lane, int wm, int wn,
    float acc[4][4][4])
{
    const uint32_t l2 = lane & 15;
    uint32_t aaddr[4], baddr[2];
    {
        uint32_t achk = (uint32_t)(ks * 2) + (lane >> 4);
#pragma unroll
        for (int i = 0; i < 4; i++) {
            uint32_t r = wm + l2 + i * 16;
            aaddr[i] = aBase + r * 64 + ((achk ^ ((r >> 1) & 3)) << 4);
        }
        uint32_t bchk = (uint32_t)(ks * 2) + ((l2 >> 3) & 1);
#pragma unroll
        for (int jj = 0; jj < 2; jj++) {
            uint32_t jt = jj * 2 + (lane >> 4);
            uint32_t r = wn + (l2 & 7) + jt * 8;
            baddr[jj] = bBase + r * 64 + ((bchk ^ ((r >> 1) & 3)) << 4);
        }
    }
    uint32_t a[4][4], b[8];
#pragma unroll
    for (int i = 0; i < 4; i++) LDSM4(a[i][0], a[i][1], a[i][2], a[i][3], aaddr[i]);
    LDSM4(b[0], b[1], b[2], b[3], baddr[0]);
    LDSM4(b[4], b[5], b[6], b[7], baddr[1]);
#pragma unroll
    for (int i = 0; i < 4; i++)
#pragma unroll
        for (int j = 0; j < 4; j++)
            MMA16816H(acc[i][j], a[i][0], a[i][1], a[i][2], a[i][3], b[2 * j], b[2 * j + 1]);
}

__device__ __forceinline__ void gemm_mainloop(
    const __half* __restrict__ A, const __half* __restrict__ Bh,
    uint32_t sb, int m0, int n0, int tid, int lane, int wm, int wn,
    float acc[4][4][4])
{
#pragma unroll
    for (int i = 0; i < 4; i++)
#pragma unroll
        for (int j = 0; j < 4; j++)
#pragma unroll
            for (int q = 0; q < 4; q++) acc[i][j][q] = 0.f;

    stage_load(sb,            A, Bh, m0, n0, 0, tid);
    CP_COMMIT();
    stage_load(sb + GM_STAGE, A, Bh, m0, n0, 1, tid);
    CP_COMMIT();

    int stage = 0;
    int lstage = 2;
    for (int kt = 0; kt < NTILES; kt++) {
        CP_WAIT1();
        __syncthreads();
        if (kt + 2 < NTILES)
            stage_load(sb + lstage * GM_STAGE, A, Bh, m0, n0, kt + 2, tid);
        CP_COMMIT();
        lstage = stage;

        const uint32_t sa = sb + stage * GM_STAGE;
        stage = (stage == 2) ? 0 : stage + 1;

#pragma unroll
        for (int ks = 0; ks < 2; ks++)
            mma_ks_body(sa, sa + 8192, ks, lane, wm, wn, acc);
    }
}

// =================================================================================
// GEMM1 fused: qk GEMM (fp16 1-term) + L2-normalize + temporal shift ->
// q/k fp16 single [img][px][ch].
// =================================================================================
__global__ void __launch_bounds__(256, 2)
gemm_qk(const __half* __restrict__ X, const __half* __restrict__ Bh,
        __half* __restrict__ qh, __half* __restrict__ kh)
{
    const bool is_k = (blockIdx.x >= 2);
    const int tt_blk = (blockIdx.y >> 3) & 7;
    if (is_k && tt_blk == 0) return;        // dead k tile (shifted away)

    extern __shared__ char smg[];
    const uint32_t sb = smem_u32(smg);
    const int tid = threadIdx.x;
    const int lane = tid & 31;
    const int wid = tid >> 5;
    const int m0 = blockIdx.y * 128;
    const int n0 = blockIdx.x * 128;
    const int wm = (wid >> 2) * 64;
    const int wn = (wid & 3) * 32;

    float acc[4][4][4];
    gemm_mainloop(X, Bh, sb, m0, n0, tid, lane, wm, wn, acc);

    const int head = (((n0 & 255) + wn) >> 5);

#pragma unroll
    for (int i = 0; i < 4; i++) {
#pragma unroll
        for (int h = 0; h < 2; h++) {
            float v0[4], v1[4];
            float ss = 0.f;
#pragma unroll
            for (int j = 0; j < 4; j++) {
                v0[j] = acc[i][j][2 * h];
                v1[j] = acc[i][j][2 * h + 1];
                ss += v0[j] * v0[j] + v1[j] * v1[j];
            }
            ss += __shfl_xor_sync(0xffffffffu, ss, 1);
            ss += __shfl_xor_sync(0xffffffffu, ss, 2);
            float inv = 1.0f / fmaxf(sqrtf(ss), 1e-12f);

            int r = m0 + wm + i * 16 + (lane >> 2) + h * 8;
            int b  = r >> 13;
            int tt = (r >> 10) & 7;
            int p  = r & 1023;

            uint32_t hw[4];
#pragma unroll
            for (int j = 0; j < 4; j++) hw[j] = h2u(v0[j] * inv, v1[j] * inv);

            if (!is_k) {
                size_t base = ((size_t)(b * 64 + head * 8 + tt) * HW + p) * 32;
#pragma unroll
                for (int j = 0; j < 4; j++) {
                    int col = j * 8 + (lane & 3) * 2;
                    *(uint32_t*)(qh + base + col) = hw[j];
                }
            } else {
                if (tt >= 1) {
                    size_t base = ((size_t)(b * 64 + head * 8 + (tt - 1)) * HW + p) * 32;
#pragma unroll
                    for (int j = 0; j < 4; j++) {
                        int col = j * 8 + (lane & 3) * 2;
                        *(uint32_t*)(kh + base + col) = hw[j];
                    }
                }
                if (tt == 7) {
                    size_t base = ((size_t)(b * 64 + head * 8 + 7) * HW + p) * 32;
#pragma unroll
                    for (int j = 0; j < 4; j++) {
                        int col = j * 8 + (lane & 3) * 2;
                        *(uint32_t*)(kh + base + col) = hw[j];
                    }
                }
            }
        }
    }
}

// =================================================================================
// GEMM4: out = v @ w_proj^T + bias (fp16 1-term), fp32 out
// =================================================================================
__global__ void __launch_bounds__(256, 2)
gemm_proj(const __half* __restrict__ V, const __half* __restrict__ Bh,
          const float* __restrict__ bias, float* __restrict__ C, int ldc)
{
    extern __shared__ char smg[];
    const uint32_t sb = smem_u32(smg);
    const int tid = threadIdx.x;
    const int lane = tid & 31;
    const int wid = tid >> 5;
    const int m0 = blockIdx.y * 128;
    const int n0 = blockIdx.x * 128;
    const int wm = (wid >> 2) * 64;
    const int wn = (wid & 3) * 32;

    float acc[4][4][4];
    gemm_mainloop(V, Bh, sb, m0, n0, tid, lane, wm, wn, acc);

#pragma unroll
    for (int j = 0; j < 4; j++) {
        int c = n0 + wn + j * 8 + (lane & 3) * 2;
        float b0 = bias[c], b1 = bias[c + 1];
#pragma unroll
        for (int i = 0; i < 4; i++) {
            int r = m0 + wm + i * 16 + (lane >> 2);
            *(float2*)(C + (size_t)r * ldc + c) =
                make_float2(acc[i][j][0] + b0, acc[i][j][1] + b1);
            *(float2*)(C + (size_t)(r + 8) * ldc + c) =
                make_float2(acc[i][j][2] + b0, acc[i][j][3] + b1);
        }
    }
}

// =================================================================================
// corr_proj (fp16-single, proven): 4 y-rows/block, 8 warps, 3 CTAs/SM.
// Epilogue emits v as single fp16.
// =================================================================================
#define CPK_K  8192u
#define CPK_W  33792u
#define CPK_CS 37888u
#define CPK_SB 54272u
#define CPK_SMEM 67584

__global__ void __launch_bounds__(256, 3)
corr_proj(const __half* __restrict__ qh, const __half* __restrict__ kh,
          const __half* __restrict__ wch, const float* __restrict__ bc,
          __half* __restrict__ v16)
{
    extern __shared__ char sm[];
    const uint32_t sb = smem_u32(sm);
    const int tid  = threadIdx.x;
    const int lane = tid & 31;
    const int w    = tid >> 5;           // warp = segment 0..7
    const int img  = blockIdx.x >> 3;
    const int yq   = (blockIdx.x & 7) * 4;

    for (int i = tid; i < 1600; i += 256)
        ((uint4*)(sm + CPK_K))[i] = make_uint4(0, 0, 0, 0);
    __syncthreads();

    for (int i = tid; i < 512; i += 256) {
        int px = i >> 2, c = i & 3;
        const __half* src = qh + ((size_t)img * HW + yq * 32 + px) * 32 + c * 8;
        uint32_t dst = sb + px * 64 + ((c ^ ((px >> 1) & 3)) << 4);
        cp16(dst, src);
    }
    for (int i = tid; i < 1280; i += 256) {
        int row = i >> 7;
        int r2  = i & 127;
        int px  = r2 >> 2;
        int c   = r2 & 3;
        int y = yq - 3 + row;
        if (y >= 0 && y < 32) {
            int rlin = row * 40 + px + 3;
            uint32_t dst = sb + CPK_K + rlin * 64 + ((c ^ ((rlin >> 1) & 3)) << 4);
            cp16(dst, kh + ((size_t)img * HW + y * 32 + px) * 32 + c * 8);
        }
    }
    {
        int r = tid >> 3, chk = tid & 7;
        uint32_t dst = sb + CPK_W + r * 128 + ((chk ^ (r & 7)) << 4);
        cp16(dst, wch + r * 64 + chk * 8);
    }
    CP_COMMIT();
    CP_WAIT0();
    __syncthreads();

    const int yloc = w >> 1;
    const int x0   = (w & 1) * 16;

    uint32_t Ah[2][4];
#pragma unroll
    for (int f = 0; f < 2; f++) {
        uint32_t r = w * 16 + (lane & 15);
        uint32_t c = f * 2 + (lane >> 4);
        uint32_t addr = sb + r * 64 + ((c ^ ((r >> 1) & 3)) << 4);
        LDSM4(Ah[f][0], Ah[f][1], Ah[f][2], Ah[f][3], addr);
    }

    float* sbuf = (float*)(sm + CPK_SB + w * 1664);
    const uint32_t cs = CPK_CS + w * 2048;
    const int lq = lane >> 2, lr = lane & 3;
    const int rr = lane >> 1;
    const int odd = lane & 1;

#pragma unroll 1
    for (int dy = 0; dy < 7; dy++) {
        const int row = yloc + dy;
        uint32_t Bt[3][4];
#pragma unroll
        for (int nt = 0; nt < 3; nt++) {
            uint32_t rlin = row * 40 + x0 + nt * 8 + (lane & 7);
            uint32_t c = lane >> 3;
            uint32_t addr = sb + CPK_K + rlin * 64 + ((c ^ ((rlin >> 1) & 3)) << 4);
            LDSM4(Bt[nt][0], Bt[nt][1], Bt[nt][2], Bt[nt][3], addr);
        }
        float acc[3][4];
#pragma unroll
        for (int nt = 0; nt < 3; nt++)
#pragma unroll
            for (int q = 0; q < 4; q++) acc[nt][q] = 0.f;

#pragma unroll
        for (int nt = 0; nt < 3; nt++) {
            MMA16816H(acc[nt], Ah[0][0], Ah[0][1], Ah[0][2], Ah[0][3], Bt[nt][0], Bt[nt][1]);
            MMA16816H(acc[nt], Ah[1][0], Ah[1][1], Ah[1][2], Ah[1][3], Bt[nt][2], Bt[nt][3]);
        }

        __syncwarp();
#pragma unroll
        for (int nt = 0; nt < 3; nt++) {
            *(float2*)&sbuf[lq * 26 + nt * 8 + lr * 2]       = make_float2(acc[nt][0], acc[nt][1]);
            *(float2*)&sbuf[(lq + 8) * 26 + nt * 8 + lr * 2] = make_float2(acc[nt][2], acc[nt][3]);
        }
        __syncwarp();

        {
            uint32_t coff = rr * 128 + ((dy ^ (rr & 7)) << 4) + odd * 8;
            if (!odd) {
                uint32_t u0 = h2u(sbuf[27 * rr + 0], sbuf[27 * rr + 1]);
                uint32_t u1 = h2u(sbuf[27 * rr + 2], sbuf[27 * rr + 3]);
                *(uint2*)(sm + cs + coff) = make_uint2(u0, u1);
            } else {
                uint32_t u0 = h2u(sbuf[27 * rr + 4], sbuf[27 * rr + 5]);
                uint32_t u1 = h2u(sbuf[27 * rr + 6], 0.f);
                *(uint2*)(sm + cs + coff) = make_uint2(u0, u1);
            }
        }
        __syncwarp();
    }

    {
        uint32_t coff = rr * 128 + ((7 ^ (rr & 7)) << 4) + odd * 8;
        *(uint2*)(sm + cs + coff) = make_uint2(0, 0);
    }
    __syncwarp();

    // Phase 2: projection m16 x n32 x k64, fp16 single
    float pacc[4][4];
#pragma unroll
    for (int n = 0; n < 4; n++)
#pragma unroll
        for (int q = 0; q < 4; q++) pacc[n][q] = 0.f;

#pragma unroll
    for (int k = 0; k < 4; k++) {
        uint32_t bh[4][2];
#pragma unroll
        for (int n = 0; n < 4; n++) {
            uint32_t wr = n * 8 + lq;
            uint32_t o0 = wr * 128 + (((2 * k)     ^ (wr & 7)) << 4) + lr * 4;
            uint32_t o1 = wr * 128 + (((2 * k + 1) ^ (wr & 7)) << 4) + lr * 4;
            bh[n][0] = *(const uint32_t*)(sm + CPK_W + o0);
            bh[n][1] = *(const uint32_t*)(sm + CPK_W + o1);
        }
        uint32_t r0 = lq, r1 = lq + 8;
        uint32_t a00 = r0 * 128 + (((2 * k)     ^ (r0 & 7)) << 4) + lr * 4;
        uint32_t a10 = r1 * 128 + (((2 * k)     ^ (r1 & 7)) << 4) + lr * 4;
        uint32_t a01 = r0 * 128 + (((2 * k + 1) ^ (r0 & 7)) << 4) + lr * 4;
        uint32_t a11 = r1 * 128 + (((2 * k + 1) ^ (r1 & 7)) << 4) + lr * 4;
        uint32_t Pa[4];
        Pa[0] = *(const uint32_t*)(sm + cs + a00);
        Pa[1] = *(const uint32_t*)(sm + cs + a10);
        Pa[2] = *(const uint32_t*)(sm + cs + a01);
        Pa[3] = *(const uint32_t*)(sm + cs + a11);
#pragma unroll
        for (int n = 0; n < 4; n++)
            MMA16816H(pacc[n], Pa[0], Pa[1], Pa[2], Pa[3], bh[n][0], bh[n][1]);
    }

    // epilogue: v + b_corr -> single fp16
    const int b    = img >> 6;
    const int head = (img >> 3) & 7;
    const int t    = img & 7;
    const int y    = yq + yloc;
    const int p0   = y * 32 + x0 + lq;
#pragma unroll
    for (int n = 0; n < 4; n++) {
        int col = n * 8 + lr * 2;
        float b0 = bc[col], b1 = bc[col + 1];
        size_t row0 = (size_t)b * N_ + t * HW + p0;
        size_t g0 = row0 * C_ + head * 32 + col;
        size_t g1 = (row0 + 8) * C_ + head * 32 + col;
        *(uint32_t*)(v16 + g0) = h2u(pacc[n][0] + b0, pacc[n][1] + b1);
        *(uint32_t*)(v16 + g1) = h2u(pacc[n][2] + b0, pacc[n][3] + b1);
    }
}

// =================================================================================
extern "C" void kernel_launch(void* const* d_in, const int* in_sizes, int n_in,
                              void* d_out, int out_size)
{
    const float* x      = (const float*)d_in[0];
    const float* w_qk   = (const float*)d_in[1];
    const float* w_corr = (const float*)d_in[2];
    const float* b_corr = (const float*)d_in[3];
    const float* w_proj = (const float*)d_in[4];
    const float* b_proj = (const float*)d_in[5];
    float* out = (float*)d_out;

    __half *qhp, *khp, *wcp, *x16, *v16, *wqk, *wpj;
    cudaGetSymbolAddress((void**)&qhp, g_qh);
    cudaGetSymbolAddress((void**)&khp, g_kh);
    cudaGetSymbolAddress((void**)&wcp, g_wcT);
    cudaGetSymbolAddress((void**)&x16, g_x16);
    cudaGetSymbolAddress((void**)&v16, g_v16);
    cudaGetSymbolAddress((void**)&wqk, g_wqk);
    cudaGetSymbolAddress((void**)&wpj, g_wpj);

    cudaFuncSetAttribute(gemm_qk,   cudaFuncAttributeMaxDynamicSharedMemorySize, GM_SMEM);
    cudaFuncSetAttribute(gemm_proj, cudaFuncAttributeMaxDynamicSharedMemorySize, GM_SMEM);
    cudaFuncSetAttribute(corr_proj, cudaFuncAttributeMaxDynamicSharedMemorySize, CPK_SMEM);

    // 0) conversions (all fp16 single)
    conv_half<<<(M_TOT * C_ / 4 + 255) / 256, 256>>>((const float4*)x, (uint2*)x16, M_TOT * C_ / 4);
    conv_half<<<(512 * 256 / 4 + 255) / 256, 256>>>((const float4*)w_qk, (uint2*)wqk, 512 * 256 / 4);
    conv_half<<<(256 * 256 / 4 + 255) / 256, 256>>>((const float4*)w_proj, (uint2*)wpj, 256 * 256 / 4);
    prep_w<<<8, 256>>>(w_corr, wcp);

    // 1) qk GEMM (fp16 1-term) + normalize + shift -> q/k fp16
    gemm_qk<<<dim3(4, 512), 256, GM_SMEM>>>(x16, wqk, qhp, khp);

    // 2) fused banded tensor-core correlation + projection -> v fp16
    corr_proj<<<BHT * 8, 256, CPK_SMEM>>>(qhp, khp, wcp, b_corr, v16);

    // 3) out = v @ w_proj^T + b_proj (fp16 1-term)
    gemm_proj<<<dim3(2, 512), 256, GM_SMEM>>>(v16, wpj, b_proj, out, 256);
}

// round 16
// speedup vs baseline: 2.2727x; 1.0998x over previous
#include <cuda_runtime.h>
#include <cuda_fp16.h>
#include <math.h>
#include <stdint.h>

#define B_    8
#define NH    8
#define T_    8
#define HD    32
#define C_    256
#define N_    8192
#define HW    1024
#define BHT   512            // B*NH*T
#define M_TOT 65536          // B*N

// ---------------- scratch (static device globals; no allocation) ----------------
__device__ __half g_qh[(size_t)BHT * HW * 32];         // q fp16 [img][px][ch]
__device__ __half g_kh[(size_t)BHT * HW * 32];         // k fp16 (shifted) [img][px][ch]
__device__ __half g_x16[(size_t)M_TOT * C_];           // x fp16
__device__ __half g_v16[(size_t)M_TOT * C_];           // v fp16
__device__ __half g_wqk[512 * 256];                    // w_qk fp16
__device__ __half g_wpj[256 * 256];                    // w_proj fp16
__device__ __half g_wcT[32 * 64];                      // w_corr fp16 [e][j'=dy*8+dx]

// ======================= asm helpers ==================
__device__ __forceinline__ uint32_t smem_u32(const void* p) {
    uint32_t a;
    asm("{ .reg .u64 t; cvta.to.shared.u64 t, %1; cvt.u32.u64 %0, t; }" : "=r"(a) : "l"(p));
    return a;
}
__device__ __forceinline__ void cp16(uint32_t saddr, const void* g) {
    asm volatile("cp.async.cg.shared.global [%0], [%1], 16;" :: "r"(saddr), "l"(g));
}
#define CP_COMMIT() asm volatile("cp.async.commit_group;" ::: "memory")
#define CP_WAIT1()  asm volatile("cp.async.wait_group 1;" ::: "memory")
#define CP_WAIT0()  asm volatile("cp.async.wait_group 0;" ::: "memory")

#define LDSM4(r0, r1, r2, r3, addr) \
    asm volatile("ldmatrix.sync.aligned.m8n8.x4.shared.b16 {%0,%1,%2,%3}, [%4];" \
                 : "=r"(r0), "=r"(r1), "=r"(r2), "=r"(r3) : "r"(addr))
#define MMA16816H(c, a0, a1, a2, a3, b0, b1) \
    asm volatile("mma.sync.aligned.m16n8k16.row.col.f32.f16.f16.f32 " \
                 "{%0,%1,%2,%3},{%4,%5,%6,%7},{%8,%9},{%0,%1,%2,%3};" \
                 : "+f"((c)[0]), "+f"((c)[1]), "+f"((c)[2]), "+f"((c)[3]) \
                 : "r"(a0), "r"(a1), "r"(a2), "r"(a3), "r"(b0), "r"(b1))

__device__ __forceinline__ uint32_t h2u(float a, float b) {
    __half2 h = __floats2half2_rn(a, b);
    return *(uint32_t*)&h;
}

// =================================================================================
// fp32 -> fp16 single, 8 float4 per thread (x conversion, DRAM-bound)
__global__ void __launch_bounds__(256)
conv_x(const float4* __restrict__ in, uint2* __restrict__ out)
{
    int base = blockIdx.x * 2048 + threadIdx.x;
#pragma unroll
    for (int j = 0; j < 8; j++) {
        int i = base + j * 256;
        float4 f = in[i];
        out[i] = make_uint2(h2u(f.x, f.y), h2u(f.z, f.w));
    }
}

// fused weight prep: w_qk -> fp16, w_proj -> fp16, w_corr -> padded [e][j'] fp16
__global__ void __launch_bounds__(256)
prep_weights(const float* __restrict__ wqk_f, const float* __restrict__ wpj_f,
             const float* __restrict__ wc_f,
             __half* __restrict__ wqk, __half* __restrict__ wpj,
             __half* __restrict__ wc)
{
    int bid = blockIdx.x;
    int tid = threadIdx.x;
    if (bid < 128) {                       // w_qk: 131072 elems = 32768 float4
        int i = bid * 256 + tid;
        float4 f = ((const float4*)wqk_f)[i];
        ((uint2*)wqk)[i] = make_uint2(h2u(f.x, f.y), h2u(f.z, f.w));
    } else if (bid < 192) {                // w_proj: 65536 elems = 16384 float4
        int i = (bid - 128) * 256 + tid;
        float4 f = ((const float4*)wpj_f)[i];
        ((uint2*)wpj)[i] = make_uint2(h2u(f.x, f.y), h2u(f.z, f.w));
    } else {                               // w_corr: 2048 padded elems, 8/thread
#pragma unroll
        for (int j = 0; j < 8; j++) {
            int i = tid * 8 + j;
            int e = i >> 6, jp = i & 63;
            int dy = jp >> 3, dx = jp & 7;
            float v = (dy < 7 && dx < 7) ? wc_f[e * 49 + dy * 7 + dx] : 0.f;
            wc[i] = __float2half(v);
        }
    }
}

// =================================================================================
// 1-term fp16 GEMM machinery (proven): 128x128 block, BK=32, K=256, 3-stage.
// =================================================================================
#define KGEMM 256
#define NTILES 8
#define GM_STAGE 16384
#define GM_SMEM  (3 * GM_STAGE)   // 49152

__device__ __forceinline__ void stage_load(
    uint32_t sbase, const __half* __restrict__ A, const __half* __restrict__ Bh,
    int m0, int n0, int kt, int tid)
{
    int row = tid >> 1;
    int cb  = (tid & 1) * 2;
#pragma unroll
    for (int j = 0; j < 2; j++) {
        int c16 = cb + j;
        uint32_t soff = (uint32_t)(row * 64 + ((c16 ^ ((row >> 1) & 3)) << 4));
        size_t ga = (size_t)row * KGEMM + kt * 32 + c16 * 8;
        cp16(sbase +    0 + soff, A  + (size_t)m0 * KGEMM + ga);
        cp16(sbase + 8192 + soff, Bh + (size_t)n0 * KGEMM + ga);
    }
}

__device__ __forceinline__ void mma_ks_body(
    uint32_t aBase, uint32_t bBase, int ks, int lane, int wm, int wn,
    float acc[4][4][4])
{
    const uint32_t l2 = lane & 15;
    uint32_t aaddr[4], baddr[2];
    {
        uint32_t achk = (uint32_t)(ks * 2) + (lane >> 4);
#pragma unroll
        for (int i = 0; i < 4; i++) {
            uint32_t r = wm + l2 + i * 16;
            aaddr[i] = aBase + r * 64 + ((achk ^ ((r >> 1) & 3)) << 4);
        }
        uint32_t bchk = (uint32_t)(ks * 2) + ((l2 >> 3) & 1);
#pragma unroll
        for (int jj = 0; jj < 2; jj++) {
            uint32_t jt = jj * 2 + (lane >> 4);
            uint32_t r = wn + (l2 & 7) + jt * 8;
            baddr[jj] = bBase + r * 64 + ((bchk ^ ((r >> 1) & 3)) << 4);
        }
    }
    uint32_t a[4][4], b[8];
#pragma unroll
    for (int i = 0; i < 4; i++) LDSM4(a[i][0], a[i][1], a[i][2], a[i][3], aaddr[i]);
    LDSM4(b[0], b[1], b[2], b[3], baddr[0]);
    LDSM4(b[4], b[5], b[6], b[7], baddr[1]);
#pragma unroll
    for (int i = 0; i < 4; i++)
#pragma unroll
        for (int j = 0; j < 4; j++)
            MMA16816H(acc[i][j], a[i][0], a[i][1], a[i][2], a[i][3], b[2 * j], b[2 * j + 1]);
}

__device__ __forceinline__ void gemm_mainloop(
    const __half* __restrict__ A, const __half* __restrict__ Bh,
    uint32_t sb, int m0, int n0, int tid, int lane, int wm, int wn,
    float acc[4][4][4])
{
#pragma unroll
    for (int i = 0; i < 4; i++)
#pragma unroll
        for (int j = 0; j < 4; j++)
#pragma unroll
            for (int q = 0; q < 4; q++) acc[i][j][q] = 0.f;

    stage_load(sb,            A, Bh, m0, n0, 0, tid);
    CP_COMMIT();
    stage_load(sb + GM_STAGE, A, Bh, m0, n0, 1, tid);
    CP_COMMIT();

    int stage = 0;
    int lstage = 2;
    for (int kt = 0; kt < NTILES; kt++) {
        CP_WAIT1();
        __syncthreads();
        if (kt + 2 < NTILES)
            stage_load(sb + lstage * GM_STAGE, A, Bh, m0, n0, kt + 2, tid);
        CP_COMMIT();
        lstage = stage;

        const uint32_t sa = sb + stage * GM_STAGE;
        stage = (stage == 2) ? 0 : stage + 1;

#pragma unroll
        for (int ks = 0; ks < 2; ks++)
            mma_ks_body(sa, sa + 8192, ks, lane, wm, wn, acc);
    }
}

// =================================================================================
// GEMM1 fused: qk GEMM (fp16 1-term) + L2-normalize + temporal shift ->
// q/k fp16 single [img][px][ch].
// =================================================================================
__global__ void __launch_bounds__(256, 2)
gemm_qk(const __half* __restrict__ X, const __half* __restrict__ Bh,
        __half* __restrict__ qh, __half* __restrict__ kh)
{
    const bool is_k = (blockIdx.x >= 2);
    const int tt_blk = (blockIdx.y >> 3) & 7;
    if (is_k && tt_blk == 0) return;        // dead k tile (shifted away)

    extern __shared__ char smg[];
    const uint32_t sb = smem_u32(smg);
    const int tid = threadIdx.x;
    const int lane = tid & 31;
    const int wid = tid >> 5;
    const int m0 = blockIdx.y * 128;
    const int n0 = blockIdx.x * 128;
    const int wm = (wid >> 2) * 64;
    const int wn = (wid & 3) * 32;

    float acc[4][4][4];
    gemm_mainloop(X, Bh, sb, m0, n0, tid, lane, wm, wn, acc);

    const int head = (((n0 & 255) + wn) >> 5);

#pragma unroll
    for (int i = 0; i < 4; i++) {
#pragma unroll
        for (int h = 0; h < 2; h++) {
            float v0[4], v1[4];
            float ss = 0.f;
#pragma unroll
            for (int j = 0; j < 4; j++) {
                v0[j] = acc[i][j][2 * h];
                v1[j] = acc[i][j][2 * h + 1];
                ss += v0[j] * v0[j] + v1[j] * v1[j];
            }
            ss += __shfl_xor_sync(0xffffffffu, ss, 1);
            ss += __shfl_xor_sync(0xffffffffu, ss, 2);
            float inv = 1.0f / fmaxf(sqrtf(ss), 1e-12f);

            int r = m0 + wm + i * 16 + (lane >> 2) + h * 8;
            int b  = r >> 13;
            int tt = (r >> 10) & 7;
            int p  = r & 1023;

            uint32_t hw[4];
#pragma unroll
            for (int j = 0; j < 4; j++) hw[j] = h2u(v0[j] * inv, v1[j] * inv);

            if (!is_k) {
                size_t base = ((size_t)(b * 64 + head * 8 + tt) * HW + p) * 32;
#pragma unroll
                for (int j = 0; j < 4; j++) {
                    int col = j * 8 + (lane & 3) * 2;
                    *(uint32_t*)(qh + base + col) = hw[j];
                }
            } else {
                if (tt >= 1) {
                    size_t base = ((size_t)(b * 64 + head * 8 + (tt - 1)) * HW + p) * 32;
#pragma unroll
                    for (int j = 0; j < 4; j++) {
                        int col = j * 8 + (lane & 3) * 2;
                        *(uint32_t*)(kh + base + col) = hw[j];
                    }
                }
                if (tt == 7) {
                    size_t base = ((size_t)(b * 64 + head * 8 + 7) * HW + p) * 32;
#pragma unroll
                    for (int j = 0; j < 4; j++) {
                        int col = j * 8 + (lane & 3) * 2;
                        *(uint32_t*)(kh + base + col) = hw[j];
                    }
                }
            }
        }
    }
}

// =================================================================================
// GEMM4: out = v @ w_proj^T + bias (fp16 1-term), fp32 out
// =================================================================================
__global__ void __launch_bounds__(256, 2)
gemm_proj(const __half* __restrict__ V, const __half* __restrict__ Bh,
          const float* __restrict__ bias, float* __restrict__ C, int ldc)
{
    extern __shared__ char smg[];
    const uint32_t sb = smem_u32(smg);
    const int tid = threadIdx.x;
    const int lane = tid & 31;
    const int wid = tid >> 5;
    const int m0 = blockIdx.y * 128;
    const int n0 = blockIdx.x * 128;
    const int wm = (wid >> 2) * 64;
    const int wn = (wid & 3) * 32;

    float acc[4][4][4];
    gemm_mainloop(V, Bh, sb, m0, n0, tid, lane, wm, wn, acc);

#pragma unroll
    for (int j = 0; j < 4; j++) {
        int c = n0 + wn + j * 8 + (lane & 3) * 2;
        float b0 = bias[c], b1 = bias[c + 1];
#pragma unroll
        for (int i = 0; i < 4; i++) {
            int r = m0 + wm + i * 16 + (lane >> 2);
            *(float2*)(C + (size_t)r * ldc + c) =
                make_float2(acc[i][j][0] + b0, acc[i][j][1] + b1);
            *(float2*)(C + (size_t)(r + 8) * ldc + c) =
                make_float2(acc[i][j][2] + b0, acc[i][j][3] + b1);
        }
    }
}

// =================================================================================
// corr_proj v4: fp16-single, 4 y-rows/block, 8 warps, 4 CTAs/SM (54.3 KB smem).
// Band staging buffer is fp16 and OVERLAID on the q region (q dead after A-frags;
// guarded by __syncthreads).
// smem: q/sbuf @0 (8192), k @8192 (25600), w @33792 (4096), cs @37888 (16384)
// =================================================================================
#define CPK_K  8192u
#define CPK_W  33792u
#define CPK_CS 37888u
#define CPK_SMEM 54272

__global__ void __launch_bounds__(256, 4)
corr_proj(const __half* __restrict__ qh, const __half* __restrict__ kh,
          const __half* __restrict__ wch, const float* __restrict__ bc,
          __half* __restrict__ v16)
{
    extern __shared__ char sm[];
    const uint32_t sb = smem_u32(sm);
    const int tid  = threadIdx.x;
    const int lane = tid & 31;
    const int w    = tid >> 5;           // warp = segment 0..7
    const int img  = blockIdx.x >> 3;
    const int yq   = (blockIdx.x & 7) * 4;

    // zero k region (25600 B = 1600 uint4)
    for (int i = tid; i < 1600; i += 256)
        ((uint4*)(sm + CPK_K))[i] = make_uint4(0, 0, 0, 0);
    __syncthreads();

    // q fill: 128 px x 4 chunks = 512 cp16
    for (int i = tid; i < 512; i += 256) {
        int px = i >> 2, c = i & 3;
        const __half* src = qh + ((size_t)img * HW + yq * 32 + px) * 32 + c * 8;
        uint32_t dst = sb + px * 64 + ((c ^ ((px >> 1) & 3)) << 4);
        cp16(dst, src);
    }
    // k fill: 10 rows x 32 px x 4 chunks = 1280 cp16 (valid rows only)
    for (int i = tid; i < 1280; i += 256) {
        int row = i >> 7;
        int r2  = i & 127;
        int px  = r2 >> 2;
        int c   = r2 & 3;
        int y = yq - 3 + row;
        if (y >= 0 && y < 32) {
            int rlin = row * 40 + px + 3;
            uint32_t dst = sb + CPK_K + rlin * 64 + ((c ^ ((rlin >> 1) & 3)) << 4);
            cp16(dst, kh + ((size_t)img * HW + y * 32 + px) * 32 + c * 8);
        }
    }
    // w fill: 32 rows x 8 chunks = 256 cp16
    {
        int r = tid >> 3, chk = tid & 7;
        uint32_t dst = sb + CPK_W + r * 128 + ((chk ^ (r & 7)) << 4);
        cp16(dst, wch + r * 64 + chk * 8);
    }
    CP_COMMIT();
    CP_WAIT0();
    __syncthreads();

    const int yloc = w >> 1;
    const int x0   = (w & 1) * 16;

    // A fragments (q fp16, reused across all dy): 2 k16 chunks
    uint32_t Ah[2][4];
#pragma unroll
    for (int f = 0; f < 2; f++) {
        uint32_t r = w * 16 + (lane & 15);
        uint32_t c = f * 2 + (lane >> 4);
        uint32_t addr = sb + r * 64 + ((c ^ ((r >> 1) & 3)) << 4);
        LDSM4(Ah[f][0], Ah[f][1], Ah[f][2], Ah[f][3], addr);
    }
    __syncthreads();   // q region dead -> reused as fp16 staging buffer

    __half* sbuf16 = (__half*)(sm + w * 832);      // per warp [16][26] fp16
    const uint32_t cs = CPK_CS + w * 2048;
    const int lq = lane >> 2, lr = lane & 3;
    const int rr = lane >> 1;
    const int odd = lane & 1;

#pragma unroll 1
    for (int dy = 0; dy < 7; dy++) {
        const int row = yloc + dy;
        uint32_t Bt[3][4];
#pragma unroll
        for (int nt = 0; nt < 3; nt++) {
            uint32_t rlin = row * 40 + x0 + nt * 8 + (lane & 7);
            uint32_t c = lane >> 3;
            uint32_t addr = sb + CPK_K + rlin * 64 + ((c ^ ((rlin >> 1) & 3)) << 4);
            LDSM4(Bt[nt][0], Bt[nt][1], Bt[nt][2], Bt[nt][3], addr);
        }
        float acc[3][4];
#pragma unroll
        for (int nt = 0; nt < 3; nt++)
#pragma unroll
            for (int q = 0; q < 4; q++) acc[nt][q] = 0.f;

#pragma unroll
        for (int nt = 0; nt < 3; nt++) {
            MMA16816H(acc[nt], Ah[0][0], Ah[0][1], Ah[0][2], Ah[0][3], Bt[nt][0], Bt[nt][1]);
            MMA16816H(acc[nt], Ah[1][0], Ah[1][1], Ah[1][2], Ah[1][3], Bt[nt][2], Bt[nt][3]);
        }

        __syncwarp();
#pragma unroll
        for (int nt = 0; nt < 3; nt++) {
            *(uint32_t*)&sbuf16[lq * 26 + nt * 8 + lr * 2]       = h2u(acc[nt][0], acc[nt][1]);
            *(uint32_t*)&sbuf16[(lq + 8) * 26 + nt * 8 + lr * 2] = h2u(acc[nt][2], acc[nt][3]);
        }
        __syncwarp();

        // band extract row rr (cols rr..rr+6 = stride-27 read) -> fp16 corr buf
        {
            uint32_t coff = rr * 128 + ((dy ^ (rr & 7)) << 4) + odd * 8;
            const __half* s = sbuf16 + 27 * rr;
            if (!odd) {
                uint32_t u0 = (uint32_t)__half_as_ushort(s[0]) |
                              ((uint32_t)__half_as_ushort(s[1]) << 16);
                uint32_t u1 = (uint32_t)__half_as_ushort(s[2]) |
                              ((uint32_t)__half_as_ushort(s[3]) << 16);
                *(uint2*)(sm + cs + coff) = make_uint2(u0, u1);
            } else {
                uint32_t u0 = (uint32_t)__half_as_ushort(s[4]) |
                              ((uint32_t)__half_as_ushort(s[5]) << 16);
                uint32_t u1 = (uint32_t)__half_as_ushort(s[6]);
                *(uint2*)(sm + cs + coff) = make_uint2(u0, u1);
            }
        }
        __syncwarp();
    }

    // zero tail chunk j' = 56..63
    {
        uint32_t coff = rr * 128 + ((7 ^ (rr & 7)) << 4) + odd * 8;
        *(uint2*)(sm + cs + coff) = make_uint2(0, 0);
    }
    __syncwarp();

    // Phase 2: projection m16 x n32 x k64, fp16 single
    float pacc[4][4];
#pragma unroll
    for (int n = 0; n < 4; n++)
#pragma unroll
        for (int q = 0; q < 4; q++) pacc[n][q] = 0.f;

#pragma unroll
    for (int k = 0; k < 4; k++) {
        uint32_t bh[4][2];
#pragma unroll
        for (int n = 0; n < 4; n++) {
            uint32_t wr = n * 8 + lq;
            uint32_t o0 = wr * 128 + (((2 * k)     ^ (wr & 7)) << 4) + lr * 4;
            uint32_t o1 = wr * 128 + (((2 * k + 1) ^ (wr & 7)) << 4) + lr * 4;
            bh[n][0] = *(const uint32_t*)(sm + CPK_W + o0);
            bh[n][1] = *(const uint32_t*)(sm + CPK_W + o1);
        }
        uint32_t r0 = lq, r1 = lq + 8;
        uint32_t a00 = r0 * 128 + (((2 * k)     ^ (r0 & 7)) << 4) + lr * 4;
        uint32_t a10 = r1 * 128 + (((2 * k)     ^ (r1 & 7)) << 4) + lr * 4;
        uint32_t a01 = r0 * 128 + (((2 * k + 1) ^ (r0 & 7)) << 4) + lr * 4;
        uint32_t a11 = r1 * 128 + (((2 * k + 1) ^ (r1 & 7)) << 4) + lr * 4;
        uint32_t Pa[4];
        Pa[0] = *(const uint32_t*)(sm + cs + a00);
        Pa[1] = *(const uint32_t*)(sm + cs + a10);
        Pa[2] = *(const uint32_t*)(sm + cs + a01);
        Pa[3] = *(const uint32_t*)(sm + cs + a11);
#pragma unroll
        for (int n = 0; n < 4; n++)
            MMA16816H(pacc[n], Pa[0], Pa[1], Pa[2], Pa[3], bh[n][0], bh[n][1]);
    }

    // epilogue: v + b_corr -> single fp16
    const int b    = img >> 6;
    const int head = (img >> 3) & 7;
    const int t    = img & 7;
    const int y    = yq + yloc;
    const int p0   = y * 32 + x0 + lq;
#pragma unroll
    for (int n = 0; n < 4; n++) {
        int col = n * 8 + lr * 2;
        float b0 = bc[col], b1 = bc[col + 1];
        size_t row0 = (size_t)b * N_ + t * HW + p0;
        size_t g0 = row0 * C_ + head * 32 + col;
        size_t g1 = (row0 + 8) * C_ + head * 32 + col;
        *(uint32_t*)(v16 + g0) = h2u(pacc[n][0] + b0, pacc[n][1] + b1);
        *(uint32_t*)(v16 + g1) = h2u(pacc[n][2] + b0, pacc[n][3] + b1);
    }
}

// =================================================================================
extern "C" void kernel_launch(void* const* d_in, const int* in_sizes, int n_in,
                              void* d_out, int out_size)
{
    const float* x      = (const float*)d_in[0];
    const float* w_qk   = (const float*)d_in[1];
    const float* w_corr = (const float*)d_in[2];
    const float* b_corr = (const float*)d_in[3];
    const float* w_proj = (const float*)d_in[4];
    const float* b_proj = (const float*)d_in[5];
    float* out = (float*)d_out;

    __half *qhp, *khp, *wcp, *x16, *v16, *wqk, *wpj;
    cudaGetSymbolAddress((void**)&qhp, g_qh);
    cudaGetSymbolAddress((void**)&khp, g_kh);
    cudaGetSymbolAddress((void**)&wcp, g_wcT);
    cudaGetSymbolAddress((void**)&x16, g_x16);
    cudaGetSymbolAddress((void**)&v16, g_v16);
    cudaGetSymbolAddress((void**)&wqk, g_wqk);
    cudaGetSymbolAddress((void**)&wpj, g_wpj);

    cudaFuncSetAttribute(gemm_qk,   cudaFuncAttributeMaxDynamicSharedMemorySize, GM_SMEM);
    cudaFuncSetAttribute(gemm_proj, cudaFuncAttributeMaxDynamicSharedMemorySize, GM_SMEM);
    cudaFuncSetAttribute(corr_proj, cudaFuncAttributeMaxDynamicSharedMemorySize, CPK_SMEM);

    // 0) conversions: x wide (8 float4/thread), weights fused into one launch
    conv_x<<<M_TOT * C_ / 4 / 2048, 256>>>((const float4*)x, (uint2*)x16);
    prep_weights<<<193, 256>>>(w_qk, w_proj, w_corr, wqk, wpj, wcp);

    // 1) qk GEMM (fp16 1-term) + normalize + shift -> q/k fp16
    gemm_qk<<<dim3(4, 512), 256, GM_SMEM>>>(x16, wqk, qhp, khp);

    // 2) fused banded tensor-core correlation + projection (4 CTAs/SM) -> v fp16
    corr_proj<<<BHT * 8, 256, CPK_SMEM>>>(qhp, khp, wcp, b_corr, v16);

    // 3) out = v @ w_proj^T + b_proj (fp16 1-term)
    gemm_proj<<<dim3(2, 512), 256, GM_SMEM>>>(v16, wpj, b_proj, out, 256);
}